// round 15
// baseline (speedup 1.0000x reference)
#include <cuda_runtime.h>
#include <cuda_fp16.h>
#include <math.h>
#include <float.h>

#define NROWS 16384      // B*N
#define NPTS  4096
#define KNN   16
#define RTOT  (NROWS*KNN)   // 262144

// ---------------- scratch (static device allocations) ----------------
__device__ float  g_hpre[NROWS*64];    // fc1 output (pre-bn1)
__device__ float  g_qkv[NROWS*64];     // q only (fp32, stride 64)
__device__ __half g_kvh[NROWS*128];    // k|v (fp16, stride 128)
__device__ int    g_idx[NROWS*KNN];
__device__ __half g_T[RTOT*64];        // T in fp16
__device__ __half g_vvh[RTOT*64];      // vv in fp16
__device__ float  g_agg[NROWS*64];
__device__ float  g_ypre[NROWS*64];
__device__ float  g_part[128*128];     // bn partial sums
__device__ float  g_bnstat[6*64];      // mu/rs x 3

// ---------------- helpers ---------------------------------------------------
__device__ __forceinline__ float tf32r(float f) {
    unsigned r;
    asm("cvt.rna.tf32.f32 %0, %1;" : "=r"(r) : "f"(f));
    return __uint_as_float(r);
}

__device__ __forceinline__ void mma_tf32(float (&d)[4], const unsigned (&a)[4],
                                         unsigned b0, unsigned b1) {
    asm volatile(
        "mma.sync.aligned.m16n8k8.row.col.f32.tf32.tf32.f32 "
        "{%0,%1,%2,%3}, {%4,%5,%6,%7}, {%8,%9}, {%0,%1,%2,%3};"
        : "+f"(d[0]), "+f"(d[1]), "+f"(d[2]), "+f"(d[3])
        : "r"(a[0]), "r"(a[1]), "r"(a[2]), "r"(a[3]), "r"(b0), "r"(b1));
}

__device__ __forceinline__ void mma_f16(float (&d)[4], const unsigned (&a)[4],
                                        unsigned b0, unsigned b1) {
    asm volatile(
        "mma.sync.aligned.m16n8k16.row.col.f32.f16.f16.f32 "
        "{%0,%1,%2,%3}, {%4,%5,%6,%7}, {%8,%9}, {%0,%1,%2,%3};"
        : "+f"(d[0]), "+f"(d[1]), "+f"(d[2]), "+f"(d[3])
        : "r"(a[0]), "r"(a[1]), "r"(a[2]), "r"(a[3]), "r"(b0), "r"(b1));
}

// ---------------- split-tf32 GEMM with fused bn-relu A-staging -------------
// mode 0: plain A ; 1: relu(bnA(A)) ; 2: relu(bnA(A)) + relu(bnB(A2))
// qkvSplit: colBase==0 -> fp32 q (cstride 64); colBase>=64 -> fp16 to CoutH.
__global__ __launch_bounds__(256) void gemm_fused_kernel(
    const float* __restrict__ A, const float* __restrict__ A2,
    const float* __restrict__ W, const float* __restrict__ bias,
    float* __restrict__ Cout, __half* __restrict__ CoutH,
    int wstride, int cstride, int mode, int qkvSplit,
    const float* __restrict__ ga, const float* __restrict__ ba,
    const float* __restrict__ mua, const float* __restrict__ rsa,
    const float* __restrict__ gb, const float* __restrict__ bb,
    const float* __restrict__ mub, const float* __restrict__ rsb)
{
    __shared__ float As[64*68];
    __shared__ float Wt[64*68];
    int tid = threadIdx.x;
    int rowBase = blockIdx.x * 64;
    int colBase = blockIdx.y * 64;

    for (int i = tid; i < 4096; i += 256) {
        int r = i >> 6, c = i & 63;
        float v = A[(rowBase + r)*64 + c];
        if (mode >= 1) v = fmaxf((v - mua[c]) * rsa[c] * ga[c] + ba[c], 0.f);
        if (mode == 2) {
            float v2 = A2[(rowBase + r)*64 + c];
            v += fmaxf((v2 - mub[c]) * rsb[c] * gb[c] + bb[c], 0.f);
        }
        As[r*68 + c] = v;
    }
    for (int i = tid; i < 4096; i += 256) {
        int k = i >> 6, n = i & 63;
        Wt[n*68 + k] = W[k*wstride + colBase + n];
    }
    __syncthreads();

    int lane = tid & 31, w = tid >> 5;
    int gid = lane >> 2, tig = lane & 3;
    int mt = w & 3, nHalf = w >> 2;
    int rb = mt * 16;

    float accH[4][4], accL[4][4];
    #pragma unroll
    for (int nt = 0; nt < 4; nt++) {
        int colE = nHalf*32 + nt*8 + 2*tig;
        float be = bias ? bias[colBase + colE]   : 0.f;
        float bo = bias ? bias[colBase + colE+1] : 0.f;
        accH[nt][0] = be; accH[nt][1] = bo;
        accH[nt][2] = be; accH[nt][3] = bo;
        accL[nt][0] = 0.f; accL[nt][1] = 0.f;
        accL[nt][2] = 0.f; accL[nt][3] = 0.f;
    }
    #pragma unroll
    for (int kb = 0; kb < 8; kb++) {
        int k0 = kb * 8;
        float af[4];
        af[0] = As[(rb + gid    )*68 + k0 + tig    ];
        af[1] = As[(rb + gid + 8)*68 + k0 + tig    ];
        af[2] = As[(rb + gid    )*68 + k0 + tig + 4];
        af[3] = As[(rb + gid + 8)*68 + k0 + tig + 4];
        unsigned ah[4], al[4];
        #pragma unroll
        for (int j = 0; j < 4; j++) {
            float hi = tf32r(af[j]);
            ah[j] = __float_as_uint(hi);
            al[j] = __float_as_uint(tf32r(af[j] - hi));
        }
        #pragma unroll
        for (int nt = 0; nt < 4; nt++) {
            int nb = nHalf*32 + nt*8;
            float bf0 = Wt[(nb + gid)*68 + k0 + tig    ];
            float bf1 = Wt[(nb + gid)*68 + k0 + tig + 4];
            float bh0f = tf32r(bf0), bh1f = tf32r(bf1);
            unsigned bh0 = __float_as_uint(bh0f);
            unsigned bh1 = __float_as_uint(bh1f);
            unsigned bl0 = __float_as_uint(tf32r(bf0 - bh0f));
            unsigned bl1 = __float_as_uint(tf32r(bf1 - bh1f));
            mma_tf32(accH[nt], ah, bh0, bh1);
            mma_tf32(accL[nt], ah, bl0, bl1);
            mma_tf32(accL[nt], al, bh0, bh1);
        }
    }
    if (qkvSplit && colBase >= 64) {
        #pragma unroll
        for (int nt = 0; nt < 4; nt++) {
            int colE = (colBase - 64) + nHalf*32 + nt*8 + 2*tig;
            *(__half2*)&CoutH[(rowBase + rb + gid    )*128 + colE] =
                __floats2half2_rn(accH[nt][0] + accL[nt][0], accH[nt][1] + accL[nt][1]);
            *(__half2*)&CoutH[(rowBase + rb + gid + 8)*128 + colE] =
                __floats2half2_rn(accH[nt][2] + accL[nt][2], accH[nt][3] + accL[nt][3]);
        }
    } else {
        int cs = qkvSplit ? 64 : cstride;
        #pragma unroll
        for (int nt = 0; nt < 4; nt++) {
            int colE = (qkvSplit ? 0 : colBase) + nHalf*32 + nt*8 + 2*tig;
            *(float2*)&Cout[(rowBase + rb + gid    )*cs + colE] =
                make_float2(accH[nt][0] + accL[nt][0], accH[nt][1] + accL[nt][1]);
            *(float2*)&Cout[(rowBase + rb + gid + 8)*cs + colE] =
                make_float2(accH[nt][2] + accL[nt][2], accH[nt][3] + accL[nt][3]);
        }
    }
}

// ---------------- BN stats phase A: coalesced partial sums -----------------
__global__ __launch_bounds__(256) void bn_statsA_kernel(const float* __restrict__ src)
{
    int b = blockIdx.x;
    int tid = threadIdx.x;
    int c = tid & 63, rsub = tid >> 6;
    float s = 0.f, s2 = 0.f;
    #pragma unroll 8
    for (int it = 0; it < 32; it++) {
        float v = src[(b*128 + it*4 + rsub)*64 + c];
        s += v; s2 += v*v;
    }
    __shared__ float sh1[256], sh2[256];
    sh1[tid] = s; sh2[tid] = s2;
    __syncthreads();
    if (tid < 64) {
        float t1 = sh1[tid] + sh1[tid+64] + sh1[tid+128] + sh1[tid+192];
        float t2 = sh2[tid] + sh2[tid+64] + sh2[tid+128] + sh2[tid+192];
        g_part[b*128 + tid]      = t1;
        g_part[b*128 + 64 + tid] = t2;
    }
}

// ---------------- BN stats phase B: parallel deterministic combine ---------
__global__ __launch_bounds__(256) void bn_statsB_kernel(float* __restrict__ mu, float* __restrict__ rs)
{
    int tid = threadIdx.x;
    int c = tid & 63, j = tid >> 6;
    float s = 0.f, s2 = 0.f;
    #pragma unroll 8
    for (int i = 0; i < 32; i++) {
        int b = j*32 + i;
        s  += g_part[b*128 + c];
        s2 += g_part[b*128 + 64 + c];
    }
    __shared__ float sh1[256], sh2[256];
    sh1[j*64 + c] = s; sh2[j*64 + c] = s2;
    __syncthreads();
    if (tid < 64) {
        float t1 = ((sh1[c] + sh1[64 + c]) + sh1[128 + c]) + sh1[192 + c];
        float t2 = ((sh2[c] + sh2[64 + c]) + sh2[128 + c]) + sh2[192 + c];
        float m = t1 / (float)NROWS;
        float var = t2 / (float)NROWS - m*m;
        mu[c] = m;
        rs[c] = rsqrtf(var + 1e-5f);
    }
}

// ---------------- final BN apply + relu ------------------------------------
__global__ void bn_final_kernel(const float* __restrict__ src,
                                const float* __restrict__ gam,
                                const float* __restrict__ bet,
                                const float* __restrict__ mu,
                                const float* __restrict__ rs,
                                float* __restrict__ dst)
{
    int i = blockIdx.x * 256 + threadIdx.x;
    int c = i & 63;
    dst[i] = fmaxf((src[i] - mu[c]) * rs[c] * gam[c] + bet[c], 0.f);
}

// ---------------- brute-force KNN (float4 loads, per-lane top-8) ----------
__global__ __launch_bounds__(256) void knn_kernel(const float* __restrict__ p)
{
    int b = blockIdx.y;
    extern __shared__ float sh[];
    float* px = sh;
    float* py = sh + NPTS;
    float* pz = sh + 2*NPTS;
    float* sd = sh + 3*NPTS;
    int*   si = (int*)(sd + 8*256);
    const float* pb = p + b*NPTS*3;
    for (int i = threadIdx.x; i < NPTS; i += 256) {
        px[i] = pb[3*i];
        py[i] = pb[3*i + 1];
        pz[i] = pb[3*i + 2];
    }
    __syncthreads();
    int w = threadIdx.x >> 5, lane = threadIdx.x & 31;
    float* wd = sd + w*256;
    int*   wi = si + w*256;

    for (int qq = 0; qq < 4; qq++) {
        int n = blockIdx.x*32 + w*4 + qq;
        float qx = px[n], qy = py[n], qz = pz[n];
        float dk[8]; int ik[8];
        #pragma unroll
        for (int t = 0; t < 8; t++) { dk[t] = FLT_MAX; ik[t] = 0; }
        for (int it = 0; it < 32; it++) {
            int base = it*128 + lane*4;
            float4 x4 = *(const float4*)&px[base];
            float4 y4 = *(const float4*)&py[base];
            float4 z4 = *(const float4*)&pz[base];
            float d4[4];
            d4[0] = (x4.x-qx)*(x4.x-qx) + (y4.x-qy)*(y4.x-qy) + (z4.x-qz)*(z4.x-qz);
            d4[1] = (x4.y-qx)*(x4.y-qx) + (y4.y-qy)*(y4.y-qy) + (z4.y-qz)*(z4.y-qz);
            d4[2] = (x4.z-qx)*(x4.z-qx) + (y4.z-qy)*(y4.z-qy) + (z4.z-qz)*(z4.z-qz);
            d4[3] = (x4.w-qx)*(x4.w-qx) + (y4.w-qy)*(y4.w-qy) + (z4.w-qz)*(z4.w-qz);
            #pragma unroll
            for (int j = 0; j < 4; j++) {
                float d = d4[j];
                if (d < dk[7]) {
                    dk[7] = d; ik[7] = base + j;
                    #pragma unroll
                    for (int s = 7; s > 0; --s) {
                        if (dk[s] < dk[s-1]) {
                            float td = dk[s]; dk[s] = dk[s-1]; dk[s-1] = td;
                            int   ti = ik[s]; ik[s] = ik[s-1]; ik[s-1] = ti;
                        }
                    }
                }
            }
        }
        #pragma unroll
        for (int t = 0; t < 8; t++) {
            wd[lane*8 + t] = dk[t];
            wi[lane*8 + t] = ik[t];
        }
        __syncwarp();
        int pos = 0;
        for (int t = 0; t < 16; t++) {
            float h = (pos < 8) ? wd[lane*8 + pos] : FLT_MAX;
            float v = h; int src = lane;
            #pragma unroll
            for (int off = 16; off > 0; off >>= 1) {
                float v2 = __shfl_down_sync(0xffffffffu, v, off);
                int   s2 = __shfl_down_sync(0xffffffffu, src, off);
                if (v2 < v || (v2 == v && s2 < src)) { v = v2; src = s2; }
            }
            src = __shfl_sync(0xffffffffu, src, 0);
            int wpos = __shfl_sync(0xffffffffu, pos, src);
            if (lane == 0) g_idx[((long)b*NPTS + n)*16 + t] = wi[src*8 + wpos];
            if (lane == src) pos++;
        }
        __syncwarp();
    }
}

// ---------------- pe-MLP (split-tf32 mma) + build T(fp16), vv(fp16) --------
#define BT_SMEM ((96+32+64 + 4*2304 + 4352 + 256 + 16)*4)
__global__ __launch_bounds__(256) void build_t_kernel(
    const float* __restrict__ p,
    const float* __restrict__ w1, const float* __restrict__ b1,
    const float* __restrict__ w2, const float* __restrict__ b2)
{
    extern __shared__ float bsm[];
    float* pw1s = bsm;               // 96
    float* pb1s = pw1s + 96;         // 32
    float* pb2s = pb1s + 32;         // 64
    float* w2H  = pb2s + 64;         // 64*36 [n][k]
    float* w2L  = w2H + 2304;
    float* hidH = w2L + 2304;        // 64*36 [row][h]
    float* hidL = hidH + 2304;
    float* pes  = hidL + 2304;       // 64*68
    float* qs   = pes + 4352;        // 4 x 64
    float* psm  = qs + 256;          // 4 x 3
    int tid = threadIdx.x;
    int qbase = blockIdx.x * 4;
    if (tid < 96) pw1s[tid] = w1[tid];
    if (tid < 32) pb1s[tid] = b1[tid];
    if (tid < 64) pb2s[tid] = b2[tid];
    for (int i = tid; i < 2048; i += 256) {
        int k = i >> 6, n = i & 63;
        float v = w2[i];
        float hi = tf32r(v);
        w2H[n*36 + k] = hi;
        w2L[n*36 + k] = tf32r(v - hi);
    }
    {
        int qi = tid >> 6, c = tid & 63;
        qs[tid] = g_qkv[(qbase + qi)*64 + c];
        if (tid < 12) psm[tid] = p[qbase*3 + tid];
    }
    __syncthreads();

    int rid = tid >> 2;
    int row = blockIdx.x * 64 + rid;
    int qloc = rid >> 4;
    int q = qbase + qloc;
    int b = q >> 12;
    int nb = (b << 12) + g_idx[row];

    float rx = psm[qloc*3+0] - p[nb*3+0];
    float ry = psm[qloc*3+1] - p[nb*3+1];
    float rz = psm[qloc*3+2] - p[nb*3+2];

    {
        int h0 = (tid & 3) * 8;
        #pragma unroll
        for (int j = 0; j < 8; j++) {
            int h = h0 + j;
            float t = fmaxf(rx*pw1s[h] + ry*pw1s[32+h] + rz*pw1s[64+h] + pb1s[h], 0.f);
            float hi = tf32r(t);
            hidH[rid*36 + h] = hi;
            hidL[rid*36 + h] = tf32r(t - hi);
        }
    }
    __syncthreads();

    // pe = relu_hid @ pos_w2 + pos_b2  (split-tf32, K=32)
    {
        int lane = tid & 31, w = tid >> 5;
        int gid = lane >> 2, tig = lane & 3;
        int mt = w & 3, nHalf = w >> 2;
        int rb = mt * 16;
        float acc[4][4];
        #pragma unroll
        for (int nt = 0; nt < 4; nt++) {
            int colE = nHalf*32 + nt*8 + 2*tig;
            float be = pb2s[colE], bo = pb2s[colE+1];
            acc[nt][0] = be; acc[nt][1] = bo;
            acc[nt][2] = be; acc[nt][3] = bo;
        }
        #pragma unroll
        for (int kb = 0; kb < 4; kb++) {
            int k0 = kb * 8;
            unsigned ah[4], al[4];
            ah[0] = __float_as_uint(hidH[(rb + gid    )*36 + k0 + tig    ]);
            ah[1] = __float_as_uint(hidH[(rb + gid + 8)*36 + k0 + tig    ]);
            ah[2] = __float_as_uint(hidH[(rb + gid    )*36 + k0 + tig + 4]);
            ah[3] = __float_as_uint(hidH[(rb + gid + 8)*36 + k0 + tig + 4]);
            al[0] = __float_as_uint(hidL[(rb + gid    )*36 + k0 + tig    ]);
            al[1] = __float_as_uint(hidL[(rb + gid + 8)*36 + k0 + tig    ]);
            al[2] = __float_as_uint(hidL[(rb + gid    )*36 + k0 + tig + 4]);
            al[3] = __float_as_uint(hidL[(rb + gid + 8)*36 + k0 + tig + 4]);
            #pragma unroll
            for (int nt = 0; nt < 4; nt++) {
                int nbase = nHalf*32 + nt*8;
                unsigned bh0 = __float_as_uint(w2H[(nbase + gid)*36 + k0 + tig    ]);
                unsigned bh1 = __float_as_uint(w2H[(nbase + gid)*36 + k0 + tig + 4]);
                unsigned bl0 = __float_as_uint(w2L[(nbase + gid)*36 + k0 + tig    ]);
                unsigned bl1 = __float_as_uint(w2L[(nbase + gid)*36 + k0 + tig + 4]);
                mma_tf32(acc[nt], ah, bh0, bh1);
                mma_tf32(acc[nt], ah, bl0, bl1);
                mma_tf32(acc[nt], al, bh0, bh1);
            }
        }
        #pragma unroll
        for (int nt = 0; nt < 4; nt++) {
            int colE = nHalf*32 + nt*8 + 2*tig;
            *(float2*)&pes[(rb + gid    )*68 + colE] = make_float2(acc[nt][0], acc[nt][1]);
            *(float2*)&pes[(rb + gid + 8)*68 + colE] = make_float2(acc[nt][2], acc[nt][3]);
        }
    }
    __syncthreads();

    int ch = (tid & 3) * 16;
    #pragma unroll
    for (int v4 = 0; v4 < 4; v4++) {
        int c = ch + v4*4;
        float4 t1 = *(const float4*)&qs[qloc*64 + c];
        uint2 kk = *(const uint2*)&g_kvh[nb*128 + c];
        uint2 vv = *(const uint2*)&g_kvh[nb*128 + 64 + c];
        float2 k01 = __half22float2(*(__half2*)&kk.x);
        float2 k23 = __half22float2(*(__half2*)&kk.y);
        float2 w01 = __half22float2(*(__half2*)&vv.x);
        float2 w23 = __half22float2(*(__half2*)&vv.y);
        float4 pe = *(const float4*)&pes[rid*68 + c];
        *(__half2*)&g_T[row*64 + c    ] =
            __floats2half2_rn(t1.x - k01.x + pe.x, t1.y - k01.y + pe.y);
        *(__half2*)&g_T[row*64 + c + 2] =
            __floats2half2_rn(t1.z - k23.x + pe.z, t1.w - k23.y + pe.w);
        *(__half2*)&g_vvh[row*64 + c    ] =
            __floats2half2_rn(w01.x + pe.x, w01.y + pe.y);
        *(__half2*)&g_vvh[row*64 + c + 2] =
            __floats2half2_rn(w23.x + pe.z, w23.y + pe.w);
    }
}

// ---------------- fused attention MLP (fp16 mma) + softmax + agg -----------
// vv tile now staged in SMEM (coalesced) alongside ts.
#define AT_FBASE  320
#define W1T_H_OFF 0                         // [256][72] halfs
#define W2T_H_OFF (256*72)                  // [64][264]
#define TS_H_OFF  (W2T_H_OFF + 64*264)      // [64][72]
#define VS_H_OFF  (TS_H_OFF + 64*72)        // [64][72]
#define HS_H_OFF  (VS_H_OFF + 64*72)        // [64][264]
#define AT_HALFS  (HS_H_OFF + 64*264)
#define ATTN_SMEM (AT_FBASE*4 + AT_HALFS*2)

__global__ __launch_bounds__(256) void attn_fused_kernel(
    const float* __restrict__ W1, const float* __restrict__ B1,
    const float* __restrict__ W2, const float* __restrict__ B2,
    int tilesPerCta)
{
    extern __shared__ float sh[];
    float* b1s = sh;
    float* b2s = sh + 256;
    __half* hb  = (__half*)(sh + AT_FBASE);
    __half* w1t = hb + W1T_H_OFF;
    __half* w2t = hb + W2T_H_OFF;
    __half* ts  = hb + TS_H_OFF;
    __half* vs  = hb + VS_H_OFF;
    __half* hs  = hb + HS_H_OFF;
    int tid = threadIdx.x;

    for (int i = tid; i < 64*256; i += 256) {
        int k = i >> 8, n = i & 255;
        w1t[n*72 + k] = __float2half(W1[i]);
    }
    for (int i = tid; i < 256*64; i += 256) {
        int k = i >> 6, n = i & 63;
        w2t[n*264 + k] = __float2half(W2[i]);
    }
    b1s[tid] = B1[tid];
    if (tid < 64) b2s[tid] = B2[tid];

    int lane = tid & 31, w = tid >> 5;
    int gid = lane >> 2, tig = lane & 3;
    int mPair  = w & 1;
    int nGroup = w >> 1;
    int mt2    = w & 3;
    int nHalf  = w >> 2;

    for (int t = 0; t < tilesPerCta; t++) {
        int rowBase = (blockIdx.x * tilesPerCta + t) * 64;
        __syncthreads();
        for (int i = tid; i < 512; i += 256) {
            int r = i >> 3, c8 = (i & 7) * 8;
            *(uint4*)&ts[r*72 + c8] = *(const uint4*)&g_T[(rowBase + r)*64 + c8];
            *(uint4*)&vs[r*72 + c8] = *(const uint4*)&g_vvh[(rowBase + r)*64 + c8];
        }
        __syncthreads();

        // ---------- layer 1: H = relu(T @ W1 + b1), K=64 ----------
        float acc1[2][8][4];
        #pragma unroll
        for (int mt = 0; mt < 2; mt++)
            #pragma unroll
            for (int nt = 0; nt < 8; nt++) {
                int colE = nGroup*64 + nt*8 + 2*tig;
                float be = b1s[colE], bo = b1s[colE + 1];
                acc1[mt][nt][0] = be; acc1[mt][nt][1] = bo;
                acc1[mt][nt][2] = be; acc1[mt][nt][3] = bo;
            }
        #pragma unroll
        for (int kb = 0; kb < 4; kb++) {
            int k0 = kb * 16;
            unsigned a[2][4];
            #pragma unroll
            for (int mt = 0; mt < 2; mt++) {
                int rb = mPair*32 + mt*16;
                a[mt][0] = *(unsigned*)&ts[(rb + gid    )*72 + k0 + 2*tig    ];
                a[mt][1] = *(unsigned*)&ts[(rb + gid + 8)*72 + k0 + 2*tig    ];
                a[mt][2] = *(unsigned*)&ts[(rb + gid    )*72 + k0 + 2*tig + 8];
                a[mt][3] = *(unsigned*)&ts[(rb + gid + 8)*72 + k0 + 2*tig + 8];
            }
            #pragma unroll
            for (int nt = 0; nt < 8; nt++) {
                int nb = nGroup*64 + nt*8;
                unsigned b0 = *(unsigned*)&w1t[(nb + gid)*72 + k0 + 2*tig    ];
                unsigned b1 = *(unsigned*)&w1t[(nb + gid)*72 + k0 + 2*tig + 8];
                mma_f16(acc1[0][nt], a[0], b0, b1);
                mma_f16(acc1[1][nt], a[1], b0, b1);
            }
        }
        #pragma unroll
        for (int mt = 0; mt < 2; mt++) {
            int rb = mPair*32 + mt*16;
            #pragma unroll
            for (int nt = 0; nt < 8; nt++) {
                int colE = nGroup*64 + nt*8 + 2*tig;
                *(__half2*)&hs[(rb + gid    )*264 + colE] =
                    __floats2half2_rn(fmaxf(acc1[mt][nt][0], 0.f), fmaxf(acc1[mt][nt][1], 0.f));
                *(__half2*)&hs[(rb + gid + 8)*264 + colE] =
                    __floats2half2_rn(fmaxf(acc1[mt][nt][2], 0.f), fmaxf(acc1[mt][nt][3], 0.f));
            }
        }
        __syncthreads();

        // ---------- layer 2: sim = H @ W2 + b2, K=256 ----------
        float acc2[4][4];
        #pragma unroll
        for (int nt = 0; nt < 4; nt++) {
            int colE = nHalf*32 + nt*8 + 2*tig;
            float be = b2s[colE], bo = b2s[colE + 1];
            acc2[nt][0] = be; acc2[nt][1] = bo;
            acc2[nt][2] = be; acc2[nt][3] = bo;
        }
        int rb2 = mt2 * 16;
        #pragma unroll 4
        for (int kb = 0; kb < 16; kb++) {
            int k0 = kb * 16;
            unsigned a[4];
            a[0] = *(unsigned*)&hs[(rb2 + gid    )*264 + k0 + 2*tig    ];
            a[1] = *(unsigned*)&hs[(rb2 + gid + 8)*264 + k0 + 2*tig    ];
            a[2] = *(unsigned*)&hs[(rb2 + gid    )*264 + k0 + 2*tig + 8];
            a[3] = *(unsigned*)&hs[(rb2 + gid + 8)*264 + k0 + 2*tig + 8];
            #pragma unroll
            for (int nt = 0; nt < 4; nt++) {
                int nb = nHalf*32 + nt*8;
                unsigned b0 = *(unsigned*)&w2t[(nb + gid)*264 + k0 + 2*tig    ];
                unsigned b1 = *(unsigned*)&w2t[(nb + gid)*264 + k0 + 2*tig + 8];
                mma_f16(acc2[nt], a, b0, b1);
            }
        }

        // ---------- softmax over 16 neighbors + aggregation ----------
        int qout = (rowBase >> 4) + mt2;
        #pragma unroll
        for (int nt = 0; nt < 4; nt++) {
            int colE = nHalf*32 + nt*8 + 2*tig;
            float me = fmaxf(acc2[nt][0], acc2[nt][2]);
            float mo = fmaxf(acc2[nt][1], acc2[nt][3]);
            #pragma unroll
            for (int off = 4; off < 32; off <<= 1) {
                me = fmaxf(me, __shfl_xor_sync(0xffffffffu, me, off));
                mo = fmaxf(mo, __shfl_xor_sync(0xffffffffu, mo, off));
            }
            float e0 = __expf(acc2[nt][0] - me);
            float e1 = __expf(acc2[nt][1] - mo);
            float e2 = __expf(acc2[nt][2] - me);
            float e3 = __expf(acc2[nt][3] - mo);

            float2 v0 = __half22float2(*(const __half2*)&vs[(rb2 + gid    )*72 + colE]);
            float2 v1 = __half22float2(*(const __half2*)&vs[(rb2 + gid + 8)*72 + colE]);

            float se = e0 + e2;
            float so = e1 + e3;
            float pe = e0*v0.x + e2*v1.x;
            float po = e1*v0.y + e3*v1.y;
            #pragma unroll
            for (int off = 4; off < 32; off <<= 1) {
                se += __shfl_xor_sync(0xffffffffu, se, off);
                so += __shfl_xor_sync(0xffffffffu, so, off);
                pe += __shfl_xor_sync(0xffffffffu, pe, off);
                po += __shfl_xor_sync(0xffffffffu, po, off);
            }
            if (gid == 0) {
                float2 outv = make_float2(pe / se, po / so);
                *(float2*)&g_agg[qout*64 + colE] = outv;
            }
        }
    }
}

// ---------------- copy p into output tail ---------------------------------
__global__ void finalize_p_kernel(const float* __restrict__ p, float* __restrict__ out)
{
    int i = blockIdx.x * 256 + threadIdx.x;
    out[i] = p[i];
}

// ---------------- launch ---------------------------------------------------
extern "C" void kernel_launch(void* const* d_in, const int* in_sizes, int n_in,
                              void* d_out, int out_size)
{
    const float* x      = (const float*)d_in[0];
    const float* p      = (const float*)d_in[1];
    const float* fc1_w  = (const float*)d_in[2];
    const float* fc1_b  = (const float*)d_in[3];
    const float* bn1_g  = (const float*)d_in[4];
    const float* bn1_b  = (const float*)d_in[5];
    const float* qkv_w  = (const float*)d_in[6];
    const float* pos_w1 = (const float*)d_in[7];
    const float* pos_b1 = (const float*)d_in[8];
    const float* pos_w2 = (const float*)d_in[9];
    const float* pos_b2 = (const float*)d_in[10];
    const float* attn_w1= (const float*)d_in[11];
    const float* attn_b1= (const float*)d_in[12];
    const float* attn_w2= (const float*)d_in[13];
    const float* attn_b2= (const float*)d_in[14];
    const float* bn2_g  = (const float*)d_in[15];
    const float* bn2_b  = (const float*)d_in[16];
    const float* fc2_w  = (const float*)d_in[17];
    const float* fc2_b  = (const float*)d_in[18];
    const float* bn3_g  = (const float*)d_in[19];
    const float* bn3_b  = (const float*)d_in[20];
    float* out = (float*)d_out;

    float *hpre, *qkv, *agg, *ypre, *bnstat;
    __half* kvh;
    cudaGetSymbolAddress((void**)&hpre, g_hpre);
    cudaGetSymbolAddress((void**)&qkv,  g_qkv);
    cudaGetSymbolAddress((void**)&kvh,  g_kvh);
    cudaGetSymbolAddress((void**)&agg,  g_agg);
    cudaGetSymbolAddress((void**)&ypre, g_ypre);
    cudaGetSymbolAddress((void**)&bnstat, g_bnstat);
    float* mu1 = bnstat;        float* rs1 = bnstat + 64;
    float* mu2 = bnstat + 128;  float* rs2 = bnstat + 192;
    float* mu3 = bnstat + 256;  float* rs3 = bnstat + 320;

    const int SMEM_KNN = (3*NPTS + 8*256)*4 + 8*256*4;
    cudaFuncSetAttribute(knn_kernel, cudaFuncAttributeMaxDynamicSharedMemorySize, SMEM_KNN);
    cudaFuncSetAttribute(attn_fused_kernel, cudaFuncAttributeMaxDynamicSharedMemorySize, ATTN_SMEM);
    cudaFuncSetAttribute(build_t_kernel, cudaFuncAttributeMaxDynamicSharedMemorySize, BT_SMEM);

    // fork: knn + p-passthrough depend only on p
    cudaStream_t s1;
    cudaEvent_t eFork, eJoin;
    cudaStreamCreateWithFlags(&s1, cudaStreamNonBlocking);
    cudaEventCreateWithFlags(&eFork, cudaEventDisableTiming);
    cudaEventCreateWithFlags(&eJoin, cudaEventDisableTiming);

    cudaEventRecord(eFork, 0);
    cudaStreamWaitEvent(s1, eFork, 0);
    knn_kernel<<<dim3(128,4), 256, SMEM_KNN, s1>>>(p);
    finalize_p_kernel<<<192, 256, 0, s1>>>(p, out + NROWS*64);
    cudaEventRecord(eJoin, s1);

    // fc1 (plain) -> hpre
    gemm_fused_kernel<<<dim3(256,1), 256>>>(x, nullptr, fc1_w, fc1_b, hpre, nullptr,
        64, 64, 0, 0,
        nullptr,nullptr,nullptr,nullptr, nullptr,nullptr,nullptr,nullptr);
    // bn1 stats
    bn_statsA_kernel<<<128, 256>>>(hpre);
    bn_statsB_kernel<<<1, 256>>>(mu1, rs1);
    // qkv = relu(bn1(hpre)) @ qkv_w : q -> fp32 g_qkv, k|v -> fp16 g_kvh
    gemm_fused_kernel<<<dim3(256,3), 256>>>(hpre, nullptr, qkv_w, nullptr, qkv, kvh,
        192, 64, 1, 1,
        bn1_g, bn1_b, mu1, rs1, nullptr,nullptr,nullptr,nullptr);

    // join knn before build_t
    cudaStreamWaitEvent(0, eJoin, 0);

    // pe-MLP + T(fp16)/vv(fp16)
    build_t_kernel<<<4096, 256, BT_SMEM>>>(p, pos_w1, pos_b1, pos_w2, pos_b2);

    // fused attention MLP + softmax + aggregation (4 tiles/CTA, grid 1024)
    attn_fused_kernel<<<1024, 256, ATTN_SMEM>>>(attn_w1, attn_b1, attn_w2, attn_b2, 4);

    // bn2 stats
    bn_statsA_kernel<<<128, 256>>>(agg);
    bn_statsB_kernel<<<1, 256>>>(mu2, rs2);

    // ypre = (relu(bn2(agg)) + relu(bn1(hpre))) @ fc2_w + fc2_b
    gemm_fused_kernel<<<dim3(256,1), 256>>>(agg, hpre, fc2_w, fc2_b, ypre, nullptr,
        64, 64, 2, 0,
        bn2_g, bn2_b, mu2, rs2, bn1_g, bn1_b, mu1, rs1);

    // bn3 stats + final apply to output
    bn_statsA_kernel<<<128, 256>>>(ypre);
    bn_statsB_kernel<<<1, 256>>>(mu3, rs3);
    bn_final_kernel<<<4096, 256>>>(ypre, bn3_g, bn3_b, mu3, rs3, out);
}

// round 16
// speedup vs baseline: 1.0835x; 1.0835x over previous
#include <cuda_runtime.h>
#include <cuda_fp16.h>
#include <math.h>
#include <float.h>

#define NROWS 16384      // B*N
#define NPTS  4096
#define KNN   16
#define RTOT  (NROWS*KNN)   // 262144

// ---------------- scratch (static device allocations) ----------------
__device__ float  g_hpre[NROWS*64];    // fc1 output (pre-bn1)
__device__ float  g_qkv[NROWS*64];     // q only (fp32, stride 64)
__device__ __half g_kvh[NROWS*128];    // k|v (fp16, stride 128)
__device__ int    g_idx[NROWS*KNN];
__device__ __half g_T[RTOT*64];        // T in fp16
__device__ __half g_vvh[RTOT*64];      // vv in fp16
__device__ float  g_agg[NROWS*64];
__device__ float  g_ypre[NROWS*64];
__device__ float  g_part[256*128];     // bn partial sums (up to 256 blocks)
__device__ float  g_bnstat[6*64];      // mu/rs x 3

// ---------------- helpers ---------------------------------------------------
__device__ __forceinline__ float tf32r(float f) {
    unsigned r;
    asm("cvt.rna.tf32.f32 %0, %1;" : "=r"(r) : "f"(f));
    return __uint_as_float(r);
}

__device__ __forceinline__ void mma_tf32(float (&d)[4], const unsigned (&a)[4],
                                         unsigned b0, unsigned b1) {
    asm volatile(
        "mma.sync.aligned.m16n8k8.row.col.f32.tf32.tf32.f32 "
        "{%0,%1,%2,%3}, {%4,%5,%6,%7}, {%8,%9}, {%0,%1,%2,%3};"
        : "+f"(d[0]), "+f"(d[1]), "+f"(d[2]), "+f"(d[3])
        : "r"(a[0]), "r"(a[1]), "r"(a[2]), "r"(a[3]), "r"(b0), "r"(b1));
}

__device__ __forceinline__ void mma_f16(float (&d)[4], const unsigned (&a)[4],
                                        unsigned b0, unsigned b1) {
    asm volatile(
        "mma.sync.aligned.m16n8k16.row.col.f32.f16.f16.f32 "
        "{%0,%1,%2,%3}, {%4,%5,%6,%7}, {%8,%9}, {%0,%1,%2,%3};"
        : "+f"(d[0]), "+f"(d[1]), "+f"(d[2]), "+f"(d[3])
        : "r"(a[0]), "r"(a[1]), "r"(a[2]), "r"(a[3]), "r"(b0), "r"(b1));
}

// ---------------- split-tf32 GEMM with fused bn-relu A-staging -------------
// mode 0: plain A ; 1: relu(bnA(A)) ; 2: relu(bnA(A)) + relu(bnB(A2))
// qkvSplit: colBase==0 -> fp32 q (cstride 64); colBase>=64 -> fp16 to CoutH.
// doStats: also emit per-block column sum/sumsq partials into g_part.
__global__ __launch_bounds__(256) void gemm_fused_kernel(
    const float* __restrict__ A, const float* __restrict__ A2,
    const float* __restrict__ W, const float* __restrict__ bias,
    float* __restrict__ Cout, __half* __restrict__ CoutH,
    int wstride, int cstride, int mode, int qkvSplit, int doStats,
    const float* __restrict__ ga, const float* __restrict__ ba,
    const float* __restrict__ mua, const float* __restrict__ rsa,
    const float* __restrict__ gb, const float* __restrict__ bb,
    const float* __restrict__ mub, const float* __restrict__ rsb)
{
    __shared__ float As[64*68];
    __shared__ float Wt[64*68];
    int tid = threadIdx.x;
    int rowBase = blockIdx.x * 64;
    int colBase = blockIdx.y * 64;

    for (int i = tid; i < 4096; i += 256) {
        int r = i >> 6, c = i & 63;
        float v = A[(rowBase + r)*64 + c];
        if (mode >= 1) v = fmaxf((v - mua[c]) * rsa[c] * ga[c] + ba[c], 0.f);
        if (mode == 2) {
            float v2 = A2[(rowBase + r)*64 + c];
            v += fmaxf((v2 - mub[c]) * rsb[c] * gb[c] + bb[c], 0.f);
        }
        As[r*68 + c] = v;
    }
    for (int i = tid; i < 4096; i += 256) {
        int k = i >> 6, n = i & 63;
        Wt[n*68 + k] = W[k*wstride + colBase + n];
    }
    __syncthreads();

    int lane = tid & 31, w = tid >> 5;
    int gid = lane >> 2, tig = lane & 3;
    int mt = w & 3, nHalf = w >> 2;
    int rb = mt * 16;

    float accH[4][4], accL[4][4];
    #pragma unroll
    for (int nt = 0; nt < 4; nt++) {
        int colE = nHalf*32 + nt*8 + 2*tig;
        float be = bias ? bias[colBase + colE]   : 0.f;
        float bo = bias ? bias[colBase + colE+1] : 0.f;
        accH[nt][0] = be; accH[nt][1] = bo;
        accH[nt][2] = be; accH[nt][3] = bo;
        accL[nt][0] = 0.f; accL[nt][1] = 0.f;
        accL[nt][2] = 0.f; accL[nt][3] = 0.f;
    }
    #pragma unroll
    for (int kb = 0; kb < 8; kb++) {
        int k0 = kb * 8;
        float af[4];
        af[0] = As[(rb + gid    )*68 + k0 + tig    ];
        af[1] = As[(rb + gid + 8)*68 + k0 + tig    ];
        af[2] = As[(rb + gid    )*68 + k0 + tig + 4];
        af[3] = As[(rb + gid + 8)*68 + k0 + tig + 4];
        unsigned ah[4], al[4];
        #pragma unroll
        for (int j = 0; j < 4; j++) {
            float hi = tf32r(af[j]);
            ah[j] = __float_as_uint(hi);
            al[j] = __float_as_uint(tf32r(af[j] - hi));
        }
        #pragma unroll
        for (int nt = 0; nt < 4; nt++) {
            int nb = nHalf*32 + nt*8;
            float bf0 = Wt[(nb + gid)*68 + k0 + tig    ];
            float bf1 = Wt[(nb + gid)*68 + k0 + tig + 4];
            float bh0f = tf32r(bf0), bh1f = tf32r(bf1);
            unsigned bh0 = __float_as_uint(bh0f);
            unsigned bh1 = __float_as_uint(bh1f);
            unsigned bl0 = __float_as_uint(tf32r(bf0 - bh0f));
            unsigned bl1 = __float_as_uint(tf32r(bf1 - bh1f));
            mma_tf32(accH[nt], ah, bh0, bh1);
            mma_tf32(accL[nt], ah, bl0, bl1);
            mma_tf32(accL[nt], al, bh0, bh1);
        }
    }
    if (qkvSplit && colBase >= 64) {
        #pragma unroll
        for (int nt = 0; nt < 4; nt++) {
            int colE = (colBase - 64) + nHalf*32 + nt*8 + 2*tig;
            *(__half2*)&CoutH[(rowBase + rb + gid    )*128 + colE] =
                __floats2half2_rn(accH[nt][0] + accL[nt][0], accH[nt][1] + accL[nt][1]);
            *(__half2*)&CoutH[(rowBase + rb + gid + 8)*128 + colE] =
                __floats2half2_rn(accH[nt][2] + accL[nt][2], accH[nt][3] + accL[nt][3]);
        }
    } else {
        int cs = qkvSplit ? 64 : cstride;
        #pragma unroll
        for (int nt = 0; nt < 4; nt++) {
            int colE = (qkvSplit ? 0 : colBase) + nHalf*32 + nt*8 + 2*tig;
            *(float2*)&Cout[(rowBase + rb + gid    )*cs + colE] =
                make_float2(accH[nt][0] + accL[nt][0], accH[nt][1] + accL[nt][1]);
            *(float2*)&Cout[(rowBase + rb + gid + 8)*cs + colE] =
                make_float2(accH[nt][2] + accL[nt][2], accH[nt][3] + accL[nt][3]);
        }
    }

    // ---- fused BN stats partials (deterministic, reuses As/Wt) ----
    if (doStats) {
        __syncthreads();               // done reading As/Wt
        int contrib = mt*8 + gid;      // 0..31 contributors per column
        #pragma unroll
        for (int nt = 0; nt < 4; nt++) {
            int colE = nHalf*32 + nt*8 + 2*tig;
            float v0 = accH[nt][0] + accL[nt][0];
            float v1 = accH[nt][1] + accL[nt][1];
            float v2 = accH[nt][2] + accL[nt][2];
            float v3 = accH[nt][3] + accL[nt][3];
            As[colE*32 + contrib]     = v0 + v2;
            Wt[colE*32 + contrib]     = v0*v0 + v2*v2;
            As[(colE+1)*32 + contrib] = v1 + v3;
            Wt[(colE+1)*32 + contrib] = v1*v1 + v3*v3;
        }
        __syncthreads();
        if (tid < 64) {
            float s = 0.f, s2 = 0.f;
            #pragma unroll 8
            for (int i = 0; i < 32; i++) {
                s  += As[tid*32 + i];
                s2 += Wt[tid*32 + i];
            }
            g_part[blockIdx.x*128 + tid]      = s;
            g_part[blockIdx.x*128 + 64 + tid] = s2;
        }
    }
}

// ---------------- BN stats phase A: coalesced partial sums (for agg) -------
__global__ __launch_bounds__(256) void bn_statsA_kernel(const float* __restrict__ src)
{
    int b = blockIdx.x;
    int tid = threadIdx.x;
    int c = tid & 63, rsub = tid >> 6;
    float s = 0.f, s2 = 0.f;
    #pragma unroll 8
    for (int it = 0; it < 32; it++) {
        float v = src[(b*128 + it*4 + rsub)*64 + c];
        s += v; s2 += v*v;
    }
    __shared__ float sh1[256], sh2[256];
    sh1[tid] = s; sh2[tid] = s2;
    __syncthreads();
    if (tid < 64) {
        float t1 = sh1[tid] + sh1[tid+64] + sh1[tid+128] + sh1[tid+192];
        float t2 = sh2[tid] + sh2[tid+64] + sh2[tid+128] + sh2[tid+192];
        g_part[b*128 + tid]      = t1;
        g_part[b*128 + 64 + tid] = t2;
    }
}

// ---------------- BN stats phase B: parallel deterministic combine ---------
__global__ __launch_bounds__(256) void bn_statsB_kernel(
    float* __restrict__ mu, float* __restrict__ rs, int nblocks)
{
    int tid = threadIdx.x;
    int c = tid & 63, j = tid >> 6;
    int per = nblocks >> 2;
    float s = 0.f, s2 = 0.f;
    for (int i = 0; i < per; i++) {
        int b = j*per + i;
        s  += g_part[b*128 + c];
        s2 += g_part[b*128 + 64 + c];
    }
    __shared__ float sh1[256], sh2[256];
    sh1[j*64 + c] = s; sh2[j*64 + c] = s2;
    __syncthreads();
    if (tid < 64) {
        float t1 = ((sh1[c] + sh1[64 + c]) + sh1[128 + c]) + sh1[192 + c];
        float t2 = ((sh2[c] + sh2[64 + c]) + sh2[128 + c]) + sh2[192 + c];
        float m = t1 / (float)NROWS;
        float var = t2 / (float)NROWS - m*m;
        mu[c] = m;
        rs[c] = rsqrtf(var + 1e-5f);
    }
}

// ---------------- final BN apply + relu ------------------------------------
__global__ void bn_final_kernel(const float* __restrict__ src,
                                const float* __restrict__ gam,
                                const float* __restrict__ bet,
                                const float* __restrict__ mu,
                                const float* __restrict__ rs,
                                float* __restrict__ dst)
{
    int i = blockIdx.x * 256 + threadIdx.x;
    int c = i & 63;
    dst[i] = fmaxf((src[i] - mu[c]) * rs[c] * gam[c] + bet[c], 0.f);
}

// ---------------- brute-force KNN (float4 loads, per-lane top-8) ----------
__global__ __launch_bounds__(256) void knn_kernel(const float* __restrict__ p)
{
    int b = blockIdx.y;
    extern __shared__ float sh[];
    float* px = sh;
    float* py = sh + NPTS;
    float* pz = sh + 2*NPTS;
    float* sd = sh + 3*NPTS;
    int*   si = (int*)(sd + 8*256);
    const float* pb = p + b*NPTS*3;
    for (int i = threadIdx.x; i < NPTS; i += 256) {
        px[i] = pb[3*i];
        py[i] = pb[3*i + 1];
        pz[i] = pb[3*i + 2];
    }
    __syncthreads();
    int w = threadIdx.x >> 5, lane = threadIdx.x & 31;
    float* wd = sd + w*256;
    int*   wi = si + w*256;

    for (int qq = 0; qq < 4; qq++) {
        int n = blockIdx.x*32 + w*4 + qq;
        float qx = px[n], qy = py[n], qz = pz[n];
        float dk[8]; int ik[8];
        #pragma unroll
        for (int t = 0; t < 8; t++) { dk[t] = FLT_MAX; ik[t] = 0; }
        for (int it = 0; it < 32; it++) {
            int base = it*128 + lane*4;
            float4 x4 = *(const float4*)&px[base];
            float4 y4 = *(const float4*)&py[base];
            float4 z4 = *(const float4*)&pz[base];
            float d4[4];
            d4[0] = (x4.x-qx)*(x4.x-qx) + (y4.x-qy)*(y4.x-qy) + (z4.x-qz)*(z4.x-qz);
            d4[1] = (x4.y-qx)*(x4.y-qx) + (y4.y-qy)*(y4.y-qy) + (z4.y-qz)*(z4.y-qz);
            d4[2] = (x4.z-qx)*(x4.z-qx) + (y4.z-qy)*(y4.z-qy) + (z4.z-qz)*(z4.z-qz);
            d4[3] = (x4.w-qx)*(x4.w-qx) + (y4.w-qy)*(y4.w-qy) + (z4.w-qz)*(z4.w-qz);
            #pragma unroll
            for (int j = 0; j < 4; j++) {
                float d = d4[j];
                if (d < dk[7]) {
                    dk[7] = d; ik[7] = base + j;
                    #pragma unroll
                    for (int s = 7; s > 0; --s) {
                        if (dk[s] < dk[s-1]) {
                            float td = dk[s]; dk[s] = dk[s-1]; dk[s-1] = td;
                            int   ti = ik[s]; ik[s] = ik[s-1]; ik[s-1] = ti;
                        }
                    }
                }
            }
        }
        #pragma unroll
        for (int t = 0; t < 8; t++) {
            wd[lane*8 + t] = dk[t];
            wi[lane*8 + t] = ik[t];
        }
        __syncwarp();
        int pos = 0;
        for (int t = 0; t < 16; t++) {
            float h = (pos < 8) ? wd[lane*8 + pos] : FLT_MAX;
            float v = h; int src = lane;
            #pragma unroll
            for (int off = 16; off > 0; off >>= 1) {
                float v2 = __shfl_down_sync(0xffffffffu, v, off);
                int   s2 = __shfl_down_sync(0xffffffffu, src, off);
                if (v2 < v || (v2 == v && s2 < src)) { v = v2; src = s2; }
            }
            src = __shfl_sync(0xffffffffu, src, 0);
            int wpos = __shfl_sync(0xffffffffu, pos, src);
            if (lane == 0) g_idx[((long)b*NPTS + n)*16 + t] = wi[src*8 + wpos];
            if (lane == src) pos++;
        }
        __syncwarp();
    }
}

// ---------------- pe-MLP (split-tf32 mma) + build T(fp16), vv(fp16) --------
#define BT_SMEM ((96+32+64 + 4*2304 + 4352 + 256 + 16)*4)
__global__ __launch_bounds__(256) void build_t_kernel(
    const float* __restrict__ p,
    const float* __restrict__ w1, const float* __restrict__ b1,
    const float* __restrict__ w2, const float* __restrict__ b2)
{
    extern __shared__ float bsm[];
    float* pw1s = bsm;               // 96
    float* pb1s = pw1s + 96;         // 32
    float* pb2s = pb1s + 32;         // 64
    float* w2H  = pb2s + 64;         // 64*36 [n][k]
    float* w2L  = w2H + 2304;
    float* hidH = w2L + 2304;        // 64*36 [row][h]
    float* hidL = hidH + 2304;
    float* pes  = hidL + 2304;       // 64*68
    float* qs   = pes + 4352;        // 4 x 64
    float* psm  = qs + 256;          // 4 x 3
    int tid = threadIdx.x;
    int qbase = blockIdx.x * 4;
    if (tid < 96) pw1s[tid] = w1[tid];
    if (tid < 32) pb1s[tid] = b1[tid];
    if (tid < 64) pb2s[tid] = b2[tid];
    for (int i = tid; i < 2048; i += 256) {
        int k = i >> 6, n = i & 63;
        float v = w2[i];
        float hi = tf32r(v);
        w2H[n*36 + k] = hi;
        w2L[n*36 + k] = tf32r(v - hi);
    }
    {
        int qi = tid >> 6, c = tid & 63;
        qs[tid] = g_qkv[(qbase + qi)*64 + c];
        if (tid < 12) psm[tid] = p[qbase*3 + tid];
    }
    __syncthreads();

    int rid = tid >> 2;
    int row = blockIdx.x * 64 + rid;
    int qloc = rid >> 4;
    int q = qbase + qloc;
    int b = q >> 12;
    int nb = (b << 12) + g_idx[row];

    float rx = psm[qloc*3+0] - p[nb*3+0];
    float ry = psm[qloc*3+1] - p[nb*3+1];
    float rz = psm[qloc*3+2] - p[nb*3+2];

    {
        int h0 = (tid & 3) * 8;
        #pragma unroll
        for (int j = 0; j < 8; j++) {
            int h = h0 + j;
            float t = fmaxf(rx*pw1s[h] + ry*pw1s[32+h] + rz*pw1s[64+h] + pb1s[h], 0.f);
            float hi = tf32r(t);
            hidH[rid*36 + h] = hi;
            hidL[rid*36 + h] = tf32r(t - hi);
        }
    }
    __syncthreads();

    // pe = relu_hid @ pos_w2 + pos_b2  (split-tf32, K=32)
    {
        int lane = tid & 31, w = tid >> 5;
        int gid = lane >> 2, tig = lane & 3;
        int mt = w & 3, nHalf = w >> 2;
        int rb = mt * 16;
        float acc[4][4];
        #pragma unroll
        for (int nt = 0; nt < 4; nt++) {
            int colE = nHalf*32 + nt*8 + 2*tig;
            float be = pb2s[colE], bo = pb2s[colE+1];
            acc[nt][0] = be; acc[nt][1] = bo;
            acc[nt][2] = be; acc[nt][3] = bo;
        }
        #pragma unroll
        for (int kb = 0; kb < 4; kb++) {
            int k0 = kb * 8;
            unsigned ah[4], al[4];
            ah[0] = __float_as_uint(hidH[(rb + gid    )*36 + k0 + tig    ]);
            ah[1] = __float_as_uint(hidH[(rb + gid + 8)*36 + k0 + tig    ]);
            ah[2] = __float_as_uint(hidH[(rb + gid    )*36 + k0 + tig + 4]);
            ah[3] = __float_as_uint(hidH[(rb + gid + 8)*36 + k0 + tig + 4]);
            al[0] = __float_as_uint(hidL[(rb + gid    )*36 + k0 + tig    ]);
            al[1] = __float_as_uint(hidL[(rb + gid + 8)*36 + k0 + tig    ]);
            al[2] = __float_as_uint(hidL[(rb + gid    )*36 + k0 + tig + 4]);
            al[3] = __float_as_uint(hidL[(rb + gid + 8)*36 + k0 + tig + 4]);
            #pragma unroll
            for (int nt = 0; nt < 4; nt++) {
                int nbase = nHalf*32 + nt*8;
                unsigned bh0 = __float_as_uint(w2H[(nbase + gid)*36 + k0 + tig    ]);
                unsigned bh1 = __float_as_uint(w2H[(nbase + gid)*36 + k0 + tig + 4]);
                unsigned bl0 = __float_as_uint(w2L[(nbase + gid)*36 + k0 + tig    ]);
                unsigned bl1 = __float_as_uint(w2L[(nbase + gid)*36 + k0 + tig + 4]);
                mma_tf32(acc[nt], ah, bh0, bh1);
                mma_tf32(acc[nt], ah, bl0, bl1);
                mma_tf32(acc[nt], al, bh0, bh1);
            }
        }
        #pragma unroll
        for (int nt = 0; nt < 4; nt++) {
            int colE = nHalf*32 + nt*8 + 2*tig;
            *(float2*)&pes[(rb + gid    )*68 + colE] = make_float2(acc[nt][0], acc[nt][1]);
            *(float2*)&pes[(rb + gid + 8)*68 + colE] = make_float2(acc[nt][2], acc[nt][3]);
        }
    }
    __syncthreads();

    int ch = (tid & 3) * 16;
    #pragma unroll
    for (int v4 = 0; v4 < 4; v4++) {
        int c = ch + v4*4;
        float4 t1 = *(const float4*)&qs[qloc*64 + c];
        uint2 kk = *(const uint2*)&g_kvh[nb*128 + c];
        uint2 vv = *(const uint2*)&g_kvh[nb*128 + 64 + c];
        float2 k01 = __half22float2(*(__half2*)&kk.x);
        float2 k23 = __half22float2(*(__half2*)&kk.y);
        float2 w01 = __half22float2(*(__half2*)&vv.x);
        float2 w23 = __half22float2(*(__half2*)&vv.y);
        float4 pe = *(const float4*)&pes[rid*68 + c];
        *(__half2*)&g_T[row*64 + c    ] =
            __floats2half2_rn(t1.x - k01.x + pe.x, t1.y - k01.y + pe.y);
        *(__half2*)&g_T[row*64 + c + 2] =
            __floats2half2_rn(t1.z - k23.x + pe.z, t1.w - k23.y + pe.w);
        *(__half2*)&g_vvh[row*64 + c    ] =
            __floats2half2_rn(w01.x + pe.x, w01.y + pe.y);
        *(__half2*)&g_vvh[row*64 + c + 2] =
            __floats2half2_rn(w23.x + pe.z, w23.y + pe.w);
    }
}

// ---------------- fused attention MLP (fp16 mma) + softmax + agg -----------
#define AT_FBASE  320
#define W1T_H_OFF 0                         // [256][72] halfs
#define W2T_H_OFF (256*72)                  // [64][264]
#define TS_H_OFF  (W2T_H_OFF + 64*264)      // [64][72]
#define HS_H_OFF  (TS_H_OFF + 64*72)        // [64][264]
#define AT_HALFS  (HS_H_OFF + 64*264)
#define ATTN_SMEM (AT_FBASE*4 + AT_HALFS*2)

__global__ __launch_bounds__(256) void attn_fused_kernel(
    const float* __restrict__ W1, const float* __restrict__ B1,
    const float* __restrict__ W2, const float* __restrict__ B2,
    int tilesPerCta)
{
    extern __shared__ float sh[];
    float* b1s = sh;
    float* b2s = sh + 256;
    __half* hb  = (__half*)(sh + AT_FBASE);
    __half* w1t = hb + W1T_H_OFF;
    __half* w2t = hb + W2T_H_OFF;
    __half* ts  = hb + TS_H_OFF;
    __half* hs  = hb + HS_H_OFF;
    int tid = threadIdx.x;

    for (int i = tid; i < 64*256; i += 256) {
        int k = i >> 8, n = i & 255;
        w1t[n*72 + k] = __float2half(W1[i]);
    }
    for (int i = tid; i < 256*64; i += 256) {
        int k = i >> 6, n = i & 63;
        w2t[n*264 + k] = __float2half(W2[i]);
    }
    b1s[tid] = B1[tid];
    if (tid < 64) b2s[tid] = B2[tid];

    int lane = tid & 31, w = tid >> 5;
    int gid = lane >> 2, tig = lane & 3;
    int mPair  = w & 1;
    int nGroup = w >> 1;
    int mt2    = w & 3;
    int nHalf  = w >> 2;

    for (int t = 0; t < tilesPerCta; t++) {
        int rowBase = (blockIdx.x * tilesPerCta + t) * 64;
        __syncthreads();
        for (int i = tid; i < 512; i += 256) {
            int r = i >> 3, c8 = (i & 7) * 8;
            *(uint4*)&ts[r*72 + c8] = *(const uint4*)&g_T[(rowBase + r)*64 + c8];
        }
        __syncthreads();

        // ---------- layer 1: H = relu(T @ W1 + b1), K=64 ----------
        float acc1[2][8][4];
        #pragma unroll
        for (int mt = 0; mt < 2; mt++)
            #pragma unroll
            for (int nt = 0; nt < 8; nt++) {
                int colE = nGroup*64 + nt*8 + 2*tig;
                float be = b1s[colE], bo = b1s[colE + 1];
                acc1[mt][nt][0] = be; acc1[mt][nt][1] = bo;
                acc1[mt][nt][2] = be; acc1[mt][nt][3] = bo;
            }
        #pragma unroll
        for (int kb = 0; kb < 4; kb++) {
            int k0 = kb * 16;
            unsigned a[2][4];
            #pragma unroll
            for (int mt = 0; mt < 2; mt++) {
                int rb = mPair*32 + mt*16;
                a[mt][0] = *(unsigned*)&ts[(rb + gid    )*72 + k0 + 2*tig    ];
                a[mt][1] = *(unsigned*)&ts[(rb + gid + 8)*72 + k0 + 2*tig    ];
                a[mt][2] = *(unsigned*)&ts[(rb + gid    )*72 + k0 + 2*tig + 8];
                a[mt][3] = *(unsigned*)&ts[(rb + gid + 8)*72 + k0 + 2*tig + 8];
            }
            #pragma unroll
            for (int nt = 0; nt < 8; nt++) {
                int nb = nGroup*64 + nt*8;
                unsigned b0 = *(unsigned*)&w1t[(nb + gid)*72 + k0 + 2*tig    ];
                unsigned b1 = *(unsigned*)&w1t[(nb + gid)*72 + k0 + 2*tig + 8];
                mma_f16(acc1[0][nt], a[0], b0, b1);
                mma_f16(acc1[1][nt], a[1], b0, b1);
            }
        }
        #pragma unroll
        for (int mt = 0; mt < 2; mt++) {
            int rb = mPair*32 + mt*16;
            #pragma unroll
            for (int nt = 0; nt < 8; nt++) {
                int colE = nGroup*64 + nt*8 + 2*tig;
                *(__half2*)&hs[(rb + gid    )*264 + colE] =
                    __floats2half2_rn(fmaxf(acc1[mt][nt][0], 0.f), fmaxf(acc1[mt][nt][1], 0.f));
                *(__half2*)&hs[(rb + gid + 8)*264 + colE] =
                    __floats2half2_rn(fmaxf(acc1[mt][nt][2], 0.f), fmaxf(acc1[mt][nt][3], 0.f));
            }
        }
        __syncthreads();

        // ---------- layer 2: sim = H @ W2 + b2, K=256 ----------
        float acc2[4][4];
        #pragma unroll
        for (int nt = 0; nt < 4; nt++) {
            int colE = nHalf*32 + nt*8 + 2*tig;
            float be = b2s[colE], bo = b2s[colE + 1];
            acc2[nt][0] = be; acc2[nt][1] = bo;
            acc2[nt][2] = be; acc2[nt][3] = bo;
        }
        int rb2 = mt2 * 16;
        #pragma unroll 4
        for (int kb = 0; kb < 16; kb++) {
            int k0 = kb * 16;
            unsigned a[4];
            a[0] = *(unsigned*)&hs[(rb2 + gid    )*264 + k0 + 2*tig    ];
            a[1] = *(unsigned*)&hs[(rb2 + gid + 8)*264 + k0 + 2*tig    ];
            a[2] = *(unsigned*)&hs[(rb2 + gid    )*264 + k0 + 2*tig + 8];
            a[3] = *(unsigned*)&hs[(rb2 + gid + 8)*264 + k0 + 2*tig + 8];
            #pragma unroll
            for (int nt = 0; nt < 4; nt++) {
                int nb = nHalf*32 + nt*8;
                unsigned b0 = *(unsigned*)&w2t[(nb + gid)*264 + k0 + 2*tig    ];
                unsigned b1 = *(unsigned*)&w2t[(nb + gid)*264 + k0 + 2*tig + 8];
                mma_f16(acc2[nt], a, b0, b1);
            }
        }

        // ---------- softmax over 16 neighbors + aggregation ----------
        int qrow = rowBase + mt2*16;
        int qout = (rowBase >> 4) + mt2;
        #pragma unroll
        for (int nt = 0; nt < 4; nt++) {
            int colE = nHalf*32 + nt*8 + 2*tig;
            float me = fmaxf(acc2[nt][0], acc2[nt][2]);
            float mo = fmaxf(acc2[nt][1], acc2[nt][3]);
            #pragma unroll
            for (int off = 4; off < 32; off <<= 1) {
                me = fmaxf(me, __shfl_xor_sync(0xffffffffu, me, off));
                mo = fmaxf(mo, __shfl_xor_sync(0xffffffffu, mo, off));
            }
            float e0 = __expf(acc2[nt][0] - me);
            float e1 = __expf(acc2[nt][1] - mo);
            float e2 = __expf(acc2[nt][2] - me);
            float e3 = __expf(acc2[nt][3] - mo);

            float2 v0 = __half22float2(*(const __half2*)&g_vvh[(qrow + gid    )*64 + colE]);
            float2 v1 = __half22float2(*(const __half2*)&g_vvh[(qrow + gid + 8)*64 + colE]);

            float se = e0 + e2;
            float so = e1 + e3;
            float pe = e0*v0.x + e2*v1.x;
            float po = e1*v0.y + e3*v1.y;
            #pragma unroll
            for (int off = 4; off < 32; off <<= 1) {
                se += __shfl_xor_sync(0xffffffffu, se, off);
                so += __shfl_xor_sync(0xffffffffu, so, off);
                pe += __shfl_xor_sync(0xffffffffu, pe, off);
                po += __shfl_xor_sync(0xffffffffu, po, off);
            }
            if (gid == 0) {
                float2 outv = make_float2(pe / se, po / so);
                *(float2*)&g_agg[qout*64 + colE] = outv;
            }
        }
    }
}

// ---------------- copy p into output tail ---------------------------------
__global__ void finalize_p_kernel(const float* __restrict__ p, float* __restrict__ out)
{
    int i = blockIdx.x * 256 + threadIdx.x;
    out[i] = p[i];
}

// ---------------- launch ---------------------------------------------------
extern "C" void kernel_launch(void* const* d_in, const int* in_sizes, int n_in,
                              void* d_out, int out_size)
{
    const float* x      = (const float*)d_in[0];
    const float* p      = (const float*)d_in[1];
    const float* fc1_w  = (const float*)d_in[2];
    const float* fc1_b  = (const float*)d_in[3];
    const float* bn1_g  = (const float*)d_in[4];
    const float* bn1_b  = (const float*)d_in[5];
    const float* qkv_w  = (const float*)d_in[6];
    const float* pos_w1 = (const float*)d_in[7];
    const float* pos_b1 = (const float*)d_in[8];
    const float* pos_w2 = (const float*)d_in[9];
    const float* pos_b2 = (const float*)d_in[10];
    const float* attn_w1= (const float*)d_in[11];
    const float* attn_b1= (const float*)d_in[12];
    const float* attn_w2= (const float*)d_in[13];
    const float* attn_b2= (const float*)d_in[14];
    const float* bn2_g  = (const float*)d_in[15];
    const float* bn2_b  = (const float*)d_in[16];
    const float* fc2_w  = (const float*)d_in[17];
    const float* fc2_b  = (const float*)d_in[18];
    const float* bn3_g  = (const float*)d_in[19];
    const float* bn3_b  = (const float*)d_in[20];
    float* out = (float*)d_out;

    float *hpre, *qkv, *agg, *ypre, *bnstat;
    __half* kvh;
    cudaGetSymbolAddress((void**)&hpre, g_hpre);
    cudaGetSymbolAddress((void**)&qkv,  g_qkv);
    cudaGetSymbolAddress((void**)&kvh,  g_kvh);
    cudaGetSymbolAddress((void**)&agg,  g_agg);
    cudaGetSymbolAddress((void**)&ypre, g_ypre);
    cudaGetSymbolAddress((void**)&bnstat, g_bnstat);
    float* mu1 = bnstat;        float* rs1 = bnstat + 64;
    float* mu2 = bnstat + 128;  float* rs2 = bnstat + 192;
    float* mu3 = bnstat + 256;  float* rs3 = bnstat + 320;

    const int SMEM_KNN = (3*NPTS + 8*256)*4 + 8*256*4;
    cudaFuncSetAttribute(knn_kernel, cudaFuncAttributeMaxDynamicSharedMemorySize, SMEM_KNN);
    cudaFuncSetAttribute(attn_fused_kernel, cudaFuncAttributeMaxDynamicSharedMemorySize, ATTN_SMEM);
    cudaFuncSetAttribute(build_t_kernel, cudaFuncAttributeMaxDynamicSharedMemorySize, BT_SMEM);

    // fork: knn + p-passthrough depend only on p
    cudaStream_t s1;
    cudaEvent_t eFork, eJoin;
    cudaStreamCreateWithFlags(&s1, cudaStreamNonBlocking);
    cudaEventCreateWithFlags(&eFork, cudaEventDisableTiming);
    cudaEventCreateWithFlags(&eJoin, cudaEventDisableTiming);

    cudaEventRecord(eFork, 0);
    cudaStreamWaitEvent(s1, eFork, 0);
    knn_kernel<<<dim3(128,4), 256, SMEM_KNN, s1>>>(p);
    finalize_p_kernel<<<192, 256, 0, s1>>>(p, out + NROWS*64);
    cudaEventRecord(eJoin, s1);

    // fc1 (plain, fused stats) -> hpre ; bn1 from 256 partials
    gemm_fused_kernel<<<dim3(256,1), 256>>>(x, nullptr, fc1_w, fc1_b, hpre, nullptr,
        64, 64, 0, 0, 1,
        nullptr,nullptr,nullptr,nullptr, nullptr,nullptr,nullptr,nullptr);
    bn_statsB_kernel<<<1, 256>>>(mu1, rs1, 256);
    // qkv = relu(bn1(hpre)) @ qkv_w : q -> fp32 g_qkv, k|v -> fp16 g_kvh
    gemm_fused_kernel<<<dim3(256,3), 256>>>(hpre, nullptr, qkv_w, nullptr, qkv, kvh,
        192, 64, 1, 1, 0,
        bn1_g, bn1_b, mu1, rs1, nullptr,nullptr,nullptr,nullptr);

    // join knn before build_t
    cudaStreamWaitEvent(0, eJoin, 0);

    // pe-MLP + T(fp16)/vv(fp16)
    build_t_kernel<<<4096, 256, BT_SMEM>>>(p, pos_w1, pos_b1, pos_w2, pos_b2);

    // fused attention MLP + softmax + aggregation (4 tiles/CTA, grid 1024)
    attn_fused_kernel<<<1024, 256, ATTN_SMEM>>>(attn_w1, attn_b1, attn_w2, attn_b2, 4);

    // bn2 stats on agg (standalone path, 128 partials)
    bn_statsA_kernel<<<128, 256>>>(agg);
    bn_statsB_kernel<<<1, 256>>>(mu2, rs2, 128);

    // ypre = (relu(bn2(agg)) + relu(bn1(hpre))) @ fc2_w + fc2_b  (fused stats)
    gemm_fused_kernel<<<dim3(256,1), 256>>>(agg, hpre, fc2_w, fc2_b, ypre, nullptr,
        64, 64, 2, 0, 1,
        bn2_g, bn2_b, mu2, rs2, bn1_g, bn1_b, mu1, rs1);
    bn_statsB_kernel<<<1, 256>>>(mu3, rs3, 256);
    bn_final_kernel<<<4096, 256>>>(ypre, bn3_g, bn3_b, mu3, rs3, out);
}

// round 17
// speedup vs baseline: 1.0967x; 1.0122x over previous
#include <cuda_runtime.h>
#include <cuda_fp16.h>
#include <math.h>
#include <float.h>

#define NROWS 16384      // B*N
#define NPTS  4096
#define KNN   16
#define RTOT  (NROWS*KNN)   // 262144

// ---------------- scratch (static device allocations) ----------------
__device__ float  g_hpre[NROWS*64];    // fc1 output (pre-bn1)
__device__ float  g_qkv[NROWS*64];     // q only (fp32, stride 64)
__device__ __half g_kvh[NROWS*128];    // k|v (fp16, stride 128)
__device__ int    g_idx[NROWS*KNN];
__device__ __half g_T[RTOT*64];        // T in fp16
__device__ __half g_vvh[RTOT*64];      // vv in fp16
__device__ float  g_agg[NROWS*64];
__device__ float  g_ypre[NROWS*64];
__device__ float  g_part[256*128];     // bn partial sums (up to 256 blocks)
__device__ float  g_bnstat[6*64];      // mu/rs x 3

// ---------------- helpers ---------------------------------------------------
__device__ __forceinline__ float tf32r(float f) {
    unsigned r;
    asm("cvt.rna.tf32.f32 %0, %1;" : "=r"(r) : "f"(f));
    return __uint_as_float(r);
}

__device__ __forceinline__ void mma_tf32(float (&d)[4], const unsigned (&a)[4],
                                         unsigned b0, unsigned b1) {
    asm volatile(
        "mma.sync.aligned.m16n8k8.row.col.f32.tf32.tf32.f32 "
        "{%0,%1,%2,%3}, {%4,%5,%6,%7}, {%8,%9}, {%0,%1,%2,%3};"
        : "+f"(d[0]), "+f"(d[1]), "+f"(d[2]), "+f"(d[3])
        : "r"(a[0]), "r"(a[1]), "r"(a[2]), "r"(a[3]), "r"(b0), "r"(b1));
}

__device__ __forceinline__ void mma_f16(float (&d)[4], const unsigned (&a)[4],
                                        unsigned b0, unsigned b1) {
    asm volatile(
        "mma.sync.aligned.m16n8k16.row.col.f32.f16.f16.f32 "
        "{%0,%1,%2,%3}, {%4,%5,%6,%7}, {%8,%9}, {%0,%1,%2,%3};"
        : "+f"(d[0]), "+f"(d[1]), "+f"(d[2]), "+f"(d[3])
        : "r"(a[0]), "r"(a[1]), "r"(a[2]), "r"(a[3]), "r"(b0), "r"(b1));
}

// ---------------- split-tf32 GEMM with fused bn-relu A-staging -------------
// mode 0: plain A ; 1: relu(bnA(A)) ; 2: relu(bnA(A)) + relu(bnB(A2))
// qkvSplit: colBase==0 -> fp32 q (cstride 64); colBase>=64 -> fp16 to CoutH.
// doStats: also emit per-block column sum/sumsq partials into g_part.
__global__ __launch_bounds__(256) void gemm_fused_kernel(
    const float* __restrict__ A, const float* __restrict__ A2,
    const float* __restrict__ W, const float* __restrict__ bias,
    float* __restrict__ Cout, __half* __restrict__ CoutH,
    int wstride, int cstride, int mode, int qkvSplit, int doStats,
    const float* __restrict__ ga, const float* __restrict__ ba,
    const float* __restrict__ mua, const float* __restrict__ rsa,
    const float* __restrict__ gb, const float* __restrict__ bb,
    const float* __restrict__ mub, const float* __restrict__ rsb)
{
    __shared__ float As[64*68];
    __shared__ float Wt[64*68];
    int tid = threadIdx.x;
    int rowBase = blockIdx.x * 64;
    int colBase = blockIdx.y * 64;

    for (int i = tid; i < 4096; i += 256) {
        int r = i >> 6, c = i & 63;
        float v = A[(rowBase + r)*64 + c];
        if (mode >= 1) v = fmaxf((v - mua[c]) * rsa[c] * ga[c] + ba[c], 0.f);
        if (mode == 2) {
            float v2 = A2[(rowBase + r)*64 + c];
            v += fmaxf((v2 - mub[c]) * rsb[c] * gb[c] + bb[c], 0.f);
        }
        As[r*68 + c] = v;
    }
    for (int i = tid; i < 4096; i += 256) {
        int k = i >> 6, n = i & 63;
        Wt[n*68 + k] = W[k*wstride + colBase + n];
    }
    __syncthreads();

    int lane = tid & 31, w = tid >> 5;
    int gid = lane >> 2, tig = lane & 3;
    int mt = w & 3, nHalf = w >> 2;
    int rb = mt * 16;

    float accH[4][4], accL[4][4];
    #pragma unroll
    for (int nt = 0; nt < 4; nt++) {
        int colE = nHalf*32 + nt*8 + 2*tig;
        float be = bias ? bias[colBase + colE]   : 0.f;
        float bo = bias ? bias[colBase + colE+1] : 0.f;
        accH[nt][0] = be; accH[nt][1] = bo;
        accH[nt][2] = be; accH[nt][3] = bo;
        accL[nt][0] = 0.f; accL[nt][1] = 0.f;
        accL[nt][2] = 0.f; accL[nt][3] = 0.f;
    }
    #pragma unroll
    for (int kb = 0; kb < 8; kb++) {
        int k0 = kb * 8;
        float af[4];
        af[0] = As[(rb + gid    )*68 + k0 + tig    ];
        af[1] = As[(rb + gid + 8)*68 + k0 + tig    ];
        af[2] = As[(rb + gid    )*68 + k0 + tig + 4];
        af[3] = As[(rb + gid + 8)*68 + k0 + tig + 4];
        unsigned ah[4], al[4];
        #pragma unroll
        for (int j = 0; j < 4; j++) {
            float hi = tf32r(af[j]);
            ah[j] = __float_as_uint(hi);
            al[j] = __float_as_uint(tf32r(af[j] - hi));
        }
        #pragma unroll
        for (int nt = 0; nt < 4; nt++) {
            int nb = nHalf*32 + nt*8;
            float bf0 = Wt[(nb + gid)*68 + k0 + tig    ];
            float bf1 = Wt[(nb + gid)*68 + k0 + tig + 4];
            float bh0f = tf32r(bf0), bh1f = tf32r(bf1);
            unsigned bh0 = __float_as_uint(bh0f);
            unsigned bh1 = __float_as_uint(bh1f);
            unsigned bl0 = __float_as_uint(tf32r(bf0 - bh0f));
            unsigned bl1 = __float_as_uint(tf32r(bf1 - bh1f));
            mma_tf32(accH[nt], ah, bh0, bh1);
            mma_tf32(accL[nt], ah, bl0, bl1);
            mma_tf32(accL[nt], al, bh0, bh1);
        }
    }
    if (qkvSplit && colBase >= 64) {
        #pragma unroll
        for (int nt = 0; nt < 4; nt++) {
            int colE = (colBase - 64) + nHalf*32 + nt*8 + 2*tig;
            *(__half2*)&CoutH[(rowBase + rb + gid    )*128 + colE] =
                __floats2half2_rn(accH[nt][0] + accL[nt][0], accH[nt][1] + accL[nt][1]);
            *(__half2*)&CoutH[(rowBase + rb + gid + 8)*128 + colE] =
                __floats2half2_rn(accH[nt][2] + accL[nt][2], accH[nt][3] + accL[nt][3]);
        }
    } else {
        int cs = qkvSplit ? 64 : cstride;
        #pragma unroll
        for (int nt = 0; nt < 4; nt++) {
            int colE = (qkvSplit ? 0 : colBase) + nHalf*32 + nt*8 + 2*tig;
            *(float2*)&Cout[(rowBase + rb + gid    )*cs + colE] =
                make_float2(accH[nt][0] + accL[nt][0], accH[nt][1] + accL[nt][1]);
            *(float2*)&Cout[(rowBase + rb + gid + 8)*cs + colE] =
                make_float2(accH[nt][2] + accL[nt][2], accH[nt][3] + accL[nt][3]);
        }
    }

    // ---- fused BN stats partials (deterministic, reuses As/Wt) ----
    if (doStats) {
        __syncthreads();               // done reading As/Wt
        int contrib = mt*8 + gid;      // 0..31 contributors per column
        #pragma unroll
        for (int nt = 0; nt < 4; nt++) {
            int colE = nHalf*32 + nt*8 + 2*tig;
            float v0 = accH[nt][0] + accL[nt][0];
            float v1 = accH[nt][1] + accL[nt][1];
            float v2 = accH[nt][2] + accL[nt][2];
            float v3 = accH[nt][3] + accL[nt][3];
            As[colE*32 + contrib]     = v0 + v2;
            Wt[colE*32 + contrib]     = v0*v0 + v2*v2;
            As[(colE+1)*32 + contrib] = v1 + v3;
            Wt[(colE+1)*32 + contrib] = v1*v1 + v3*v3;
        }
        __syncthreads();
        if (tid < 64) {
            float s = 0.f, s2 = 0.f;
            #pragma unroll 8
            for (int i = 0; i < 32; i++) {
                s  += As[tid*32 + i];
                s2 += Wt[tid*32 + i];
            }
            g_part[blockIdx.x*128 + tid]      = s;
            g_part[blockIdx.x*128 + 64 + tid] = s2;
        }
    }
}

// ---------------- BN stats phase A: coalesced partial sums (for agg) -------
__global__ __launch_bounds__(256) void bn_statsA_kernel(const float* __restrict__ src)
{
    int b = blockIdx.x;
    int tid = threadIdx.x;
    int c = tid & 63, rsub = tid >> 6;
    float s = 0.f, s2 = 0.f;
    #pragma unroll 8
    for (int it = 0; it < 32; it++) {
        float v = src[(b*128 + it*4 + rsub)*64 + c];
        s += v; s2 += v*v;
    }
    __shared__ float sh1[256], sh2[256];
    sh1[tid] = s; sh2[tid] = s2;
    __syncthreads();
    if (tid < 64) {
        float t1 = sh1[tid] + sh1[tid+64] + sh1[tid+128] + sh1[tid+192];
        float t2 = sh2[tid] + sh2[tid+64] + sh2[tid+128] + sh2[tid+192];
        g_part[b*128 + tid]      = t1;
        g_part[b*128 + 64 + tid] = t2;
    }
}

// ---------------- BN stats phase B: templated deterministic combine --------
template<int NB>
__global__ __launch_bounds__(256) void bn_statsB_kernel(
    float* __restrict__ mu, float* __restrict__ rs)
{
    constexpr int PER = NB / 4;
    int tid = threadIdx.x;
    int c = tid & 63, j = tid >> 6;
    float s = 0.f, s2 = 0.f;
    #pragma unroll 8
    for (int i = 0; i < PER; i++) {
        int b = j*PER + i;
        s  += g_part[b*128 + c];
        s2 += g_part[b*128 + 64 + c];
    }
    __shared__ float sh1[256], sh2[256];
    sh1[j*64 + c] = s; sh2[j*64 + c] = s2;
    __syncthreads();
    if (tid < 64) {
        float t1 = ((sh1[c] + sh1[64 + c]) + sh1[128 + c]) + sh1[192 + c];
        float t2 = ((sh2[c] + sh2[64 + c]) + sh2[128 + c]) + sh2[192 + c];
        float m = t1 / (float)NROWS;
        float var = t2 / (float)NROWS - m*m;
        mu[c] = m;
        rs[c] = rsqrtf(var + 1e-5f);
    }
}

// ---------------- final BN apply + relu ------------------------------------
__global__ void bn_final_kernel(const float* __restrict__ src,
                                const float* __restrict__ gam,
                                const float* __restrict__ bet,
                                const float* __restrict__ mu,
                                const float* __restrict__ rs,
                                float* __restrict__ dst)
{
    int i = blockIdx.x * 256 + threadIdx.x;
    int c = i & 63;
    dst[i] = fmaxf((src[i] - mu[c]) * rs[c] * gam[c] + bet[c], 0.f);
}

// ---------------- brute-force KNN (float4 loads, per-lane top-8) ----------
__global__ __launch_bounds__(256) void knn_kernel(const float* __restrict__ p)
{
    int b = blockIdx.y;
    extern __shared__ float sh[];
    float* px = sh;
    float* py = sh + NPTS;
    float* pz = sh + 2*NPTS;
    float* sd = sh + 3*NPTS;
    int*   si = (int*)(sd + 8*256);
    const float* pb = p + b*NPTS*3;
    for (int i = threadIdx.x; i < NPTS; i += 256) {
        px[i] = pb[3*i];
        py[i] = pb[3*i + 1];
        pz[i] = pb[3*i + 2];
    }
    __syncthreads();
    int w = threadIdx.x >> 5, lane = threadIdx.x & 31;
    float* wd = sd + w*256;
    int*   wi = si + w*256;

    for (int qq = 0; qq < 4; qq++) {
        int n = blockIdx.x*32 + w*4 + qq;
        float qx = px[n], qy = py[n], qz = pz[n];
        float dk[8]; int ik[8];
        #pragma unroll
        for (int t = 0; t < 8; t++) { dk[t] = FLT_MAX; ik[t] = 0; }
        for (int it = 0; it < 32; it++) {
            int base = it*128 + lane*4;
            float4 x4 = *(const float4*)&px[base];
            float4 y4 = *(const float4*)&py[base];
            float4 z4 = *(const float4*)&pz[base];
            float d4[4];
            d4[0] = (x4.x-qx)*(x4.x-qx) + (y4.x-qy)*(y4.x-qy) + (z4.x-qz)*(z4.x-qz);
            d4[1] = (x4.y-qx)*(x4.y-qx) + (y4.y-qy)*(y4.y-qy) + (z4.y-qz)*(z4.y-qz);
            d4[2] = (x4.z-qx)*(x4.z-qx) + (y4.z-qy)*(y4.z-qy) + (z4.z-qz)*(z4.z-qz);
            d4[3] = (x4.w-qx)*(x4.w-qx) + (y4.w-qy)*(y4.w-qy) + (z4.w-qz)*(z4.w-qz);
            #pragma unroll
            for (int j = 0; j < 4; j++) {
                float d = d4[j];
                if (d < dk[7]) {
                    dk[7] = d; ik[7] = base + j;
                    #pragma unroll
                    for (int s = 7; s > 0; --s) {
                        if (dk[s] < dk[s-1]) {
                            float td = dk[s]; dk[s] = dk[s-1]; dk[s-1] = td;
                            int   ti = ik[s]; ik[s] = ik[s-1]; ik[s-1] = ti;
                        }
                    }
                }
            }
        }
        #pragma unroll
        for (int t = 0; t < 8; t++) {
            wd[lane*8 + t] = dk[t];
            wi[lane*8 + t] = ik[t];
        }
        __syncwarp();
        int pos = 0;
        for (int t = 0; t < 16; t++) {
            float h = (pos < 8) ? wd[lane*8 + pos] : FLT_MAX;
            float v = h; int src = lane;
            #pragma unroll
            for (int off = 16; off > 0; off >>= 1) {
                float v2 = __shfl_down_sync(0xffffffffu, v, off);
                int   s2 = __shfl_down_sync(0xffffffffu, src, off);
                if (v2 < v || (v2 == v && s2 < src)) { v = v2; src = s2; }
            }
            src = __shfl_sync(0xffffffffu, src, 0);
            int wpos = __shfl_sync(0xffffffffu, pos, src);
            if (lane == 0) g_idx[((long)b*NPTS + n)*16 + t] = wi[src*8 + wpos];
            if (lane == src) pos++;
        }
        __syncwarp();
    }
}

// ---------------- pe-MLP (split-tf32 mma) + build T(fp16), vv(fp16) --------
#define BT_SMEM ((96+32+64 + 4*2304 + 4352 + 256 + 16)*4)
__global__ __launch_bounds__(256) void build_t_kernel(
    const float* __restrict__ p,
    const float* __restrict__ w1, const float* __restrict__ b1,
    const float* __restrict__ w2, const float* __restrict__ b2)
{
    extern __shared__ float bsm[];
    float* pw1s = bsm;               // 96
    float* pb1s = pw1s + 96;         // 32
    float* pb2s = pb1s + 32;         // 64
    float* w2H  = pb2s + 64;         // 64*36 [n][k]
    float* w2L  = w2H + 2304;
    float* hidH = w2L + 2304;        // 64*36 [row][h]
    float* hidL = hidH + 2304;
    float* pes  = hidL + 2304;       // 64*68
    float* qs   = pes + 4352;        // 4 x 64
    float* psm  = qs + 256;          // 4 x 3
    int tid = threadIdx.x;
    int qbase = blockIdx.x * 4;
    if (tid < 96) pw1s[tid] = w1[tid];
    if (tid < 32) pb1s[tid] = b1[tid];
    if (tid < 64) pb2s[tid] = b2[tid];
    for (int i = tid; i < 2048; i += 256) {
        int k = i >> 6, n = i & 63;
        float v = w2[i];
        float hi = tf32r(v);
        w2H[n*36 + k] = hi;
        w2L[n*36 + k] = tf32r(v - hi);
    }
    {
        int qi = tid >> 6, c = tid & 63;
        qs[tid] = g_qkv[(qbase + qi)*64 + c];
        if (tid < 12) psm[tid] = p[qbase*3 + tid];
    }
    __syncthreads();

    int rid = tid >> 2;
    int row = blockIdx.x * 64 + rid;
    int qloc = rid >> 4;
    int q = qbase + qloc;
    int b = q >> 12;
    int nb = (b << 12) + g_idx[row];

    float rx = psm[qloc*3+0] - p[nb*3+0];
    float ry = psm[qloc*3+1] - p[nb*3+1];
    float rz = psm[qloc*3+2] - p[nb*3+2];

    {
        int h0 = (tid & 3) * 8;
        #pragma unroll
        for (int j = 0; j < 8; j++) {
            int h = h0 + j;
            float t = fmaxf(rx*pw1s[h] + ry*pw1s[32+h] + rz*pw1s[64+h] + pb1s[h], 0.f);
            float hi = tf32r(t);
            hidH[rid*36 + h] = hi;
            hidL[rid*36 + h] = tf32r(t - hi);
        }
    }
    __syncthreads();

    // pe = relu_hid @ pos_w2 + pos_b2  (split-tf32, K=32)
    {
        int lane = tid & 31, w = tid >> 5;
        int gid = lane >> 2, tig = lane & 3;
        int mt = w & 3, nHalf = w >> 2;
        int rb = mt * 16;
        float acc[4][4];
        #pragma unroll
        for (int nt = 0; nt < 4; nt++) {
            int colE = nHalf*32 + nt*8 + 2*tig;
            float be = pb2s[colE], bo = pb2s[colE+1];
            acc[nt][0] = be; acc[nt][1] = bo;
            acc[nt][2] = be; acc[nt][3] = bo;
        }
        #pragma unroll
        for (int kb = 0; kb < 4; kb++) {
            int k0 = kb * 8;
            unsigned ah[4], al[4];
            ah[0] = __float_as_uint(hidH[(rb + gid    )*36 + k0 + tig    ]);
            ah[1] = __float_as_uint(hidH[(rb + gid + 8)*36 + k0 + tig    ]);
            ah[2] = __float_as_uint(hidH[(rb + gid    )*36 + k0 + tig + 4]);
            ah[3] = __float_as_uint(hidH[(rb + gid + 8)*36 + k0 + tig + 4]);
            al[0] = __float_as_uint(hidL[(rb + gid    )*36 + k0 + tig    ]);
            al[1] = __float_as_uint(hidL[(rb + gid + 8)*36 + k0 + tig    ]);
            al[2] = __float_as_uint(hidL[(rb + gid    )*36 + k0 + tig + 4]);
            al[3] = __float_as_uint(hidL[(rb + gid + 8)*36 + k0 + tig + 4]);
            #pragma unroll
            for (int nt = 0; nt < 4; nt++) {
                int nbase = nHalf*32 + nt*8;
                unsigned bh0 = __float_as_uint(w2H[(nbase + gid)*36 + k0 + tig    ]);
                unsigned bh1 = __float_as_uint(w2H[(nbase + gid)*36 + k0 + tig + 4]);
                unsigned bl0 = __float_as_uint(w2L[(nbase + gid)*36 + k0 + tig    ]);
                unsigned bl1 = __float_as_uint(w2L[(nbase + gid)*36 + k0 + tig + 4]);
                mma_tf32(acc[nt], ah, bh0, bh1);
                mma_tf32(acc[nt], ah, bl0, bl1);
                mma_tf32(acc[nt], al, bh0, bh1);
            }
        }
        #pragma unroll
        for (int nt = 0; nt < 4; nt++) {
            int colE = nHalf*32 + nt*8 + 2*tig;
            *(float2*)&pes[(rb + gid    )*68 + colE] = make_float2(acc[nt][0], acc[nt][1]);
            *(float2*)&pes[(rb + gid + 8)*68 + colE] = make_float2(acc[nt][2], acc[nt][3]);
        }
    }
    __syncthreads();

    int ch = (tid & 3) * 16;
    #pragma unroll
    for (int v4 = 0; v4 < 4; v4++) {
        int c = ch + v4*4;
        float4 t1 = *(const float4*)&qs[qloc*64 + c];
        uint2 kk = *(const uint2*)&g_kvh[nb*128 + c];
        uint2 vv = *(const uint2*)&g_kvh[nb*128 + 64 + c];
        float2 k01 = __half22float2(*(__half2*)&kk.x);
        float2 k23 = __half22float2(*(__half2*)&kk.y);
        float2 w01 = __half22float2(*(__half2*)&vv.x);
        float2 w23 = __half22float2(*(__half2*)&vv.y);
        float4 pe = *(const float4*)&pes[rid*68 + c];
        *(__half2*)&g_T[row*64 + c    ] =
            __floats2half2_rn(t1.x - k01.x + pe.x, t1.y - k01.y + pe.y);
        *(__half2*)&g_T[row*64 + c + 2] =
            __floats2half2_rn(t1.z - k23.x + pe.z, t1.w - k23.y + pe.w);
        *(__half2*)&g_vvh[row*64 + c    ] =
            __floats2half2_rn(w01.x + pe.x, w01.y + pe.y);
        *(__half2*)&g_vvh[row*64 + c + 2] =
            __floats2half2_rn(w23.x + pe.z, w23.y + pe.w);
    }
}

// ---------------- fused attention MLP (fp16 mma) + softmax + agg -----------
#define AT_FBASE  320
#define W1T_H_OFF 0                         // [256][72] halfs
#define W2T_H_OFF (256*72)                  // [64][264]
#define TS_H_OFF  (W2T_H_OFF + 64*264)      // [64][72]
#define HS_H_OFF  (TS_H_OFF + 64*72)        // [64][264]
#define AT_HALFS  (HS_H_OFF + 64*264)
#define ATTN_SMEM (AT_FBASE*4 + AT_HALFS*2)

__global__ __launch_bounds__(256) void attn_fused_kernel(
    const float* __restrict__ W1, const float* __restrict__ B1,
    const float* __restrict__ W2, const float* __restrict__ B2,
    int tilesPerCta)
{
    extern __shared__ float sh[];
    float* b1s = sh;
    float* b2s = sh + 256;
    __half* hb  = (__half*)(sh + AT_FBASE);
    __half* w1t = hb + W1T_H_OFF;
    __half* w2t = hb + W2T_H_OFF;
    __half* ts  = hb + TS_H_OFF;
    __half* hs  = hb + HS_H_OFF;
    int tid = threadIdx.x;

    for (int i = tid; i < 64*256; i += 256) {
        int k = i >> 8, n = i & 255;
        w1t[n*72 + k] = __float2half(W1[i]);
    }
    for (int i = tid; i < 256*64; i += 256) {
        int k = i >> 6, n = i & 63;
        w2t[n*264 + k] = __float2half(W2[i]);
    }
    b1s[tid] = B1[tid];
    if (tid < 64) b2s[tid] = B2[tid];

    int lane = tid & 31, w = tid >> 5;
    int gid = lane >> 2, tig = lane & 3;
    int mPair  = w & 1;
    int nGroup = w >> 1;
    int mt2    = w & 3;
    int nHalf  = w >> 2;

    for (int t = 0; t < tilesPerCta; t++) {
        int rowBase = (blockIdx.x * tilesPerCta + t) * 64;
        __syncthreads();
        for (int i = tid; i < 512; i += 256) {
            int r = i >> 3, c8 = (i & 7) * 8;
            *(uint4*)&ts[r*72 + c8] = *(const uint4*)&g_T[(rowBase + r)*64 + c8];
        }
        __syncthreads();

        // ---------- layer 1: H = relu(T @ W1 + b1), K=64 ----------
        float acc1[2][8][4];
        #pragma unroll
        for (int mt = 0; mt < 2; mt++)
            #pragma unroll
            for (int nt = 0; nt < 8; nt++) {
                int colE = nGroup*64 + nt*8 + 2*tig;
                float be = b1s[colE], bo = b1s[colE + 1];
                acc1[mt][nt][0] = be; acc1[mt][nt][1] = bo;
                acc1[mt][nt][2] = be; acc1[mt][nt][3] = bo;
            }
        #pragma unroll
        for (int kb = 0; kb < 4; kb++) {
            int k0 = kb * 16;
            unsigned a[2][4];
            #pragma unroll
            for (int mt = 0; mt < 2; mt++) {
                int rb = mPair*32 + mt*16;
                a[mt][0] = *(unsigned*)&ts[(rb + gid    )*72 + k0 + 2*tig    ];
                a[mt][1] = *(unsigned*)&ts[(rb + gid + 8)*72 + k0 + 2*tig    ];
                a[mt][2] = *(unsigned*)&ts[(rb + gid    )*72 + k0 + 2*tig + 8];
                a[mt][3] = *(unsigned*)&ts[(rb + gid + 8)*72 + k0 + 2*tig + 8];
            }
            #pragma unroll
            for (int nt = 0; nt < 8; nt++) {
                int nb = nGroup*64 + nt*8;
                unsigned b0 = *(unsigned*)&w1t[(nb + gid)*72 + k0 + 2*tig    ];
                unsigned b1 = *(unsigned*)&w1t[(nb + gid)*72 + k0 + 2*tig + 8];
                mma_f16(acc1[0][nt], a[0], b0, b1);
                mma_f16(acc1[1][nt], a[1], b0, b1);
            }
        }
        #pragma unroll
        for (int mt = 0; mt < 2; mt++) {
            int rb = mPair*32 + mt*16;
            #pragma unroll
            for (int nt = 0; nt < 8; nt++) {
                int colE = nGroup*64 + nt*8 + 2*tig;
                *(__half2*)&hs[(rb + gid    )*264 + colE] =
                    __floats2half2_rn(fmaxf(acc1[mt][nt][0], 0.f), fmaxf(acc1[mt][nt][1], 0.f));
                *(__half2*)&hs[(rb + gid + 8)*264 + colE] =
                    __floats2half2_rn(fmaxf(acc1[mt][nt][2], 0.f), fmaxf(acc1[mt][nt][3], 0.f));
            }
        }
        __syncthreads();

        // ---------- layer 2: sim = H @ W2 + b2, K=256 ----------
        float acc2[4][4];
        #pragma unroll
        for (int nt = 0; nt < 4; nt++) {
            int colE = nHalf*32 + nt*8 + 2*tig;
            float be = b2s[colE], bo = b2s[colE + 1];
            acc2[nt][0] = be; acc2[nt][1] = bo;
            acc2[nt][2] = be; acc2[nt][3] = bo;
        }
        int rb2 = mt2 * 16;
        #pragma unroll 4
        for (int kb = 0; kb < 16; kb++) {
            int k0 = kb * 16;
            unsigned a[4];
            a[0] = *(unsigned*)&hs[(rb2 + gid    )*264 + k0 + 2*tig    ];
            a[1] = *(unsigned*)&hs[(rb2 + gid + 8)*264 + k0 + 2*tig    ];
            a[2] = *(unsigned*)&hs[(rb2 + gid    )*264 + k0 + 2*tig + 8];
            a[3] = *(unsigned*)&hs[(rb2 + gid + 8)*264 + k0 + 2*tig + 8];
            #pragma unroll
            for (int nt = 0; nt < 4; nt++) {
                int nb = nHalf*32 + nt*8;
                unsigned b0 = *(unsigned*)&w2t[(nb + gid)*264 + k0 + 2*tig    ];
                unsigned b1 = *(unsigned*)&w2t[(nb + gid)*264 + k0 + 2*tig + 8];
                mma_f16(acc2[nt], a, b0, b1);
            }
        }

        // ---------- softmax over 16 neighbors + aggregation ----------
        int qrow = rowBase + mt2*16;
        int qout = (rowBase >> 4) + mt2;
        #pragma unroll
        for (int nt = 0; nt < 4; nt++) {
            int colE = nHalf*32 + nt*8 + 2*tig;
            float me = fmaxf(acc2[nt][0], acc2[nt][2]);
            float mo = fmaxf(acc2[nt][1], acc2[nt][3]);
            #pragma unroll
            for (int off = 4; off < 32; off <<= 1) {
                me = fmaxf(me, __shfl_xor_sync(0xffffffffu, me, off));
                mo = fmaxf(mo, __shfl_xor_sync(0xffffffffu, mo, off));
            }
            float e0 = __expf(acc2[nt][0] - me);
            float e1 = __expf(acc2[nt][1] - mo);
            float e2 = __expf(acc2[nt][2] - me);
            float e3 = __expf(acc2[nt][3] - mo);

            float2 v0 = __half22float2(*(const __half2*)&g_vvh[(qrow + gid    )*64 + colE]);
            float2 v1 = __half22float2(*(const __half2*)&g_vvh[(qrow + gid + 8)*64 + colE]);

            float se = e0 + e2;
            float so = e1 + e3;
            float pe = e0*v0.x + e2*v1.x;
            float po = e1*v0.y + e3*v1.y;
            #pragma unroll
            for (int off = 4; off < 32; off <<= 1) {
                se += __shfl_xor_sync(0xffffffffu, se, off);
                so += __shfl_xor_sync(0xffffffffu, so, off);
                pe += __shfl_xor_sync(0xffffffffu, pe, off);
                po += __shfl_xor_sync(0xffffffffu, po, off);
            }
            if (gid == 0) {
                float2 outv = make_float2(pe / se, po / so);
                *(float2*)&g_agg[qout*64 + colE] = outv;
            }
        }
    }
}

// ---------------- copy p into output tail ---------------------------------
__global__ void finalize_p_kernel(const float* __restrict__ p, float* __restrict__ out)
{
    int i = blockIdx.x * 256 + threadIdx.x;
    out[i] = p[i];
}

// ---------------- launch ---------------------------------------------------
extern "C" void kernel_launch(void* const* d_in, const int* in_sizes, int n_in,
                              void* d_out, int out_size)
{
    const float* x      = (const float*)d_in[0];
    const float* p      = (const float*)d_in[1];
    const float* fc1_w  = (const float*)d_in[2];
    const float* fc1_b  = (const float*)d_in[3];
    const float* bn1_g  = (const float*)d_in[4];
    const float* bn1_b  = (const float*)d_in[5];
    const float* qkv_w  = (const float*)d_in[6];
    const float* pos_w1 = (const float*)d_in[7];
    const float* pos_b1 = (const float*)d_in[8];
    const float* pos_w2 = (const float*)d_in[9];
    const float* pos_b2 = (const float*)d_in[10];
    const float* attn_w1= (const float*)d_in[11];
    const float* attn_b1= (const float*)d_in[12];
    const float* attn_w2= (const float*)d_in[13];
    const float* attn_b2= (const float*)d_in[14];
    const float* bn2_g  = (const float*)d_in[15];
    const float* bn2_b  = (const float*)d_in[16];
    const float* fc2_w  = (const float*)d_in[17];
    const float* fc2_b  = (const float*)d_in[18];
    const float* bn3_g  = (const float*)d_in[19];
    const float* bn3_b  = (const float*)d_in[20];
    float* out = (float*)d_out;

    float *hpre, *qkv, *agg, *ypre, *bnstat;
    __half* kvh;
    cudaGetSymbolAddress((void**)&hpre, g_hpre);
    cudaGetSymbolAddress((void**)&qkv,  g_qkv);
    cudaGetSymbolAddress((void**)&kvh,  g_kvh);
    cudaGetSymbolAddress((void**)&agg,  g_agg);
    cudaGetSymbolAddress((void**)&ypre, g_ypre);
    cudaGetSymbolAddress((void**)&bnstat, g_bnstat);
    float* mu1 = bnstat;        float* rs1 = bnstat + 64;
    float* mu2 = bnstat + 128;  float* rs2 = bnstat + 192;
    float* mu3 = bnstat + 256;  float* rs3 = bnstat + 320;

    const int SMEM_KNN = (3*NPTS + 8*256)*4 + 8*256*4;
    cudaFuncSetAttribute(knn_kernel, cudaFuncAttributeMaxDynamicSharedMemorySize, SMEM_KNN);
    cudaFuncSetAttribute(attn_fused_kernel, cudaFuncAttributeMaxDynamicSharedMemorySize, ATTN_SMEM);
    cudaFuncSetAttribute(build_t_kernel, cudaFuncAttributeMaxDynamicSharedMemorySize, BT_SMEM);

    // fork: knn + p-passthrough depend only on p
    cudaStream_t s1;
    cudaEvent_t eFork, eJoin;
    cudaStreamCreateWithFlags(&s1, cudaStreamNonBlocking);
    cudaEventCreateWithFlags(&eFork, cudaEventDisableTiming);
    cudaEventCreateWithFlags(&eJoin, cudaEventDisableTiming);

    cudaEventRecord(eFork, 0);
    cudaStreamWaitEvent(s1, eFork, 0);
    knn_kernel<<<dim3(128,4), 256, SMEM_KNN, s1>>>(p);
    finalize_p_kernel<<<192, 256, 0, s1>>>(p, out + NROWS*64);
    cudaEventRecord(eJoin, s1);

    // fc1 (plain, fused stats) -> hpre ; bn1 from 256 partials
    gemm_fused_kernel<<<dim3(256,1), 256>>>(x, nullptr, fc1_w, fc1_b, hpre, nullptr,
        64, 64, 0, 0, 1,
        nullptr,nullptr,nullptr,nullptr, nullptr,nullptr,nullptr,nullptr);
    bn_statsB_kernel<256><<<1, 256>>>(mu1, rs1);
    // qkv = relu(bn1(hpre)) @ qkv_w : q -> fp32 g_qkv, k|v -> fp16 g_kvh
    gemm_fused_kernel<<<dim3(256,3), 256>>>(hpre, nullptr, qkv_w, nullptr, qkv, kvh,
        192, 64, 1, 1, 0,
        bn1_g, bn1_b, mu1, rs1, nullptr,nullptr,nullptr,nullptr);

    // join knn before build_t
    cudaStreamWaitEvent(0, eJoin, 0);

    // pe-MLP + T(fp16)/vv(fp16)
    build_t_kernel<<<4096, 256, BT_SMEM>>>(p, pos_w1, pos_b1, pos_w2, pos_b2);

    // fused attention MLP + softmax + aggregation (4 tiles/CTA, grid 1024)
    attn_fused_kernel<<<1024, 256, ATTN_SMEM>>>(attn_w1, attn_b1, attn_w2, attn_b2, 4);

    // bn2 stats on agg (standalone path, 128 partials)
    bn_statsA_kernel<<<128, 256>>>(agg);
    bn_statsB_kernel<128><<<1, 256>>>(mu2, rs2);

    // ypre = (relu(bn2(agg)) + relu(bn1(hpre))) @ fc2_w + fc2_b  (fused stats)
    gemm_fused_kernel<<<dim3(256,1), 256>>>(agg, hpre, fc2_w, fc2_b, ypre, nullptr,
        64, 64, 2, 0, 1,
        bn2_g, bn2_b, mu2, rs2, bn1_g, bn1_b, mu1, rs1);
    bn_statsB_kernel<256><<<1, 256>>>(mu3, rs3);
    bn_final_kernel<<<4096, 256>>>(ypre, bn3_g, bn3_b, mu3, rs3, out);
}